// round 2
// baseline (speedup 1.0000x reference)
#include <cuda_runtime.h>
#include <math.h>

#define NN   50000
#define EE   1600000
#define MM   (EE + NN)
#define IND  256
#define HIDD 64
#define NH1  2
#define F1   128        // NH1*HIDD
#define NCLS 10
#define NEG  0.2f

// ---------------- scratch (static device globals; no allocation) ------------
__device__ float    g_h1[NN * F1];
__device__ float    g_as1[NN * NH1], g_ad1[NN * NH1];
__device__ unsigned g_max1[NN * NH1];
__device__ float    g_sum1[NN * NH1];
__device__ float    g_out1[NN * F1];
__device__ float    g_x2[NN * F1];
__device__ float    g_h2[NN * HIDD];
__device__ float    g_as2[NN], g_ad2[NN];
__device__ unsigned g_max2[NN];
__device__ float    g_sum2[NN];
__device__ float    g_out2[NN * HIDD];

// ---------------- helpers ----------------------------------------------------
__device__ __forceinline__ float lrelu(float x) { return x > 0.f ? x : NEG * x; }
__device__ __forceinline__ float eluf(float x)  { return x > 0.f ? x : (expf(x) - 1.f); }

// order-preserving float <-> uint encoding for atomicMax on floats
__device__ __forceinline__ unsigned fenc(float f) {
    unsigned b = __float_as_uint(f);
    return (b & 0x80000000u) ? ~b : (b | 0x80000000u);
}
__device__ __forceinline__ float fdec(unsigned e) {
    return __uint_as_float((e & 0x80000000u) ? (e ^ 0x80000000u) : ~e);
}
#define ENC_NEG_INF 0x007fffffu   // fenc(-inf)

// ---------------- init -------------------------------------------------------
template <int L>
__global__ void k_init() {
    int i = blockIdx.x * blockDim.x + threadIdx.x;
    if (L == 1) {
        if (i < NN * NH1) { g_max1[i] = ENC_NEG_INF; g_sum1[i] = 0.f; }
        if (i < NN * F1)  { g_out1[i] = 0.f; }
    } else {
        if (i < NN)        { g_max2[i] = ENC_NEG_INF; g_sum2[i] = 0.f; }
        if (i < NN * HIDD) { g_out2[i] = 0.f; }
    }
}

// ---------------- tiled fp32 GEMM: C[NN,Nc] = A[NN,K] @ B[K,Nc] --------------
// BM=64 BN=64 BK=16, 4x4 microtile, 256 threads.
template <int L>
__global__ void k_sgemm(const float* __restrict__ Ain, const float* __restrict__ B) {
    constexpr int K  = (L == 1) ? IND : F1;
    constexpr int Nc = (L == 1) ? F1  : HIDD;
    const float* A = (L == 1) ? Ain : (const float*)g_x2;
    float* C       = (L == 1) ? g_h1 : g_h2;

    __shared__ float As[16][65];   // padded: conflict-free transposed store
    __shared__ float Bs[16][64];

    int tid = threadIdx.x;
    int tx = tid & 15, ty = tid >> 4;
    int row0 = blockIdx.y * 64;
    int col0 = blockIdx.x * 64;

    float acc[4][4] = {};
    for (int k0 = 0; k0 < K; k0 += 16) {
        #pragma unroll
        for (int i = tid; i < 64 * 16; i += 256) {
            int r = i >> 4, c = i & 15;
            int gr = row0 + r;
            As[c][r] = (gr < NN) ? A[(size_t)gr * K + k0 + c] : 0.f;
        }
        #pragma unroll
        for (int i = tid; i < 16 * 64; i += 256) {
            int r = i >> 6, c = i & 63;
            Bs[r][c] = B[(size_t)(k0 + r) * Nc + col0 + c];
        }
        __syncthreads();
        #pragma unroll
        for (int kk = 0; kk < 16; kk++) {
            float a[4], b[4];
            #pragma unroll
            for (int i = 0; i < 4; i++) a[i] = As[kk][ty * 4 + i];
            #pragma unroll
            for (int j = 0; j < 4; j++) b[j] = Bs[kk][tx * 4 + j];
            #pragma unroll
            for (int i = 0; i < 4; i++)
                #pragma unroll
                for (int j = 0; j < 4; j++) acc[i][j] += a[i] * b[j];
        }
        __syncthreads();
    }
    #pragma unroll
    for (int i = 0; i < 4; i++) {
        int gr = row0 + ty * 4 + i;
        if (gr < NN) {
            #pragma unroll
            for (int j = 0; j < 4; j++)
                C[(size_t)gr * Nc + col0 + tx * 4 + j] = acc[i][j];
        }
    }
}

// ---------------- per-node attention dots: a_s[n,h]=<h[n,h,:],att_s[h,:]> ----
template <int L>
__global__ void k_attdot(const float* __restrict__ att_s, const float* __restrict__ att_d) {
    constexpr int H = (L == 1) ? NH1 : 1;
    const float* h = (L == 1) ? (const float*)g_h1 : (const float*)g_h2;
    float* as_ = (L == 1) ? g_as1 : g_as2;
    float* ad_ = (L == 1) ? g_ad1 : g_ad2;

    int w = (blockIdx.x * blockDim.x + threadIdx.x) >> 5;
    int lane = threadIdx.x & 31;
    if (w >= NN) return;
    #pragma unroll
    for (int hh = 0; hh < H; hh++) {
        float s = 0.f, d = 0.f;
        #pragma unroll
        for (int f = lane; f < HIDD; f += 32) {
            float v = h[(size_t)w * H * HIDD + hh * HIDD + f];
            s += v * att_s[hh * HIDD + f];
            d += v * att_d[hh * HIDD + f];
        }
        #pragma unroll
        for (int o = 16; o; o >>= 1) {
            s += __shfl_down_sync(0xffffffffu, s, o);
            d += __shfl_down_sync(0xffffffffu, d, o);
        }
        if (lane == 0) { as_[w * H + hh] = s; ad_[w * H + hh] = d; }
    }
}

// ---------------- edge pass 0 (segment max) / pass 1 (segment exp-sum) -------
template <int L, int PASS>
__global__ void k_edge_ms(const int* __restrict__ ei) {
    constexpr int H = (L == 1) ? NH1 : 1;
    const float* as_ = (L == 1) ? g_as1 : g_as2;
    const float* ad_ = (L == 1) ? g_ad1 : g_ad2;
    unsigned* maxb = (L == 1) ? g_max1 : g_max2;
    float*    sumb = (L == 1) ? g_sum1 : g_sum2;

    int m = blockIdx.x * blockDim.x + threadIdx.x;
    if (m >= MM) return;
    int s, d;
    if (m < EE) { s = ei[m]; d = ei[EE + m]; }
    else        { s = d = m - EE; }
    #pragma unroll
    for (int hh = 0; hh < H; hh++) {
        float e = lrelu(as_[s * H + hh] + ad_[d * H + hh]);
        if (PASS == 0) atomicMax(&maxb[d * H + hh], fenc(e));
        else           atomicAdd(&sumb[d * H + hh], expf(e - fdec(maxb[d * H + hh])));
    }
}

// ---------------- edge pass 2 (weighted aggregation): warp per message -------
template <int L>
__global__ void k_edge_agg(const int* __restrict__ ei) {
    constexpr int H = (L == 1) ? NH1 : 1;
    constexpr int F = H * HIDD;
    const float* as_     = (L == 1) ? g_as1 : g_as2;
    const float* ad_     = (L == 1) ? g_ad1 : g_ad2;
    const unsigned* maxb = (L == 1) ? g_max1 : g_max2;
    const float* sumb    = (L == 1) ? g_sum1 : g_sum2;
    const float* h       = (L == 1) ? (const float*)g_h1 : (const float*)g_h2;
    float* outb          = (L == 1) ? g_out1 : g_out2;

    int w = (blockIdx.x * blockDim.x + threadIdx.x) >> 5;
    int lane = threadIdx.x & 31;
    if (w >= MM) return;
    int s, d;
    if (w < EE) { s = ei[w]; d = ei[EE + w]; }
    else        { s = d = w - EE; }

    float alpha[H];
    #pragma unroll
    for (int hh = 0; hh < H; hh++) {
        float e = lrelu(as_[s * H + hh] + ad_[d * H + hh]);
        alpha[hh] = expf(e - fdec(maxb[d * H + hh])) / sumb[d * H + hh];
    }
    const float* hs = h + (size_t)s * F;
    float* od = outb + (size_t)d * F;
    #pragma unroll
    for (int f = lane; f < F; f += 32) {
        atomicAdd(&od[f], alpha[f / HIDD] * hs[f]);
    }
}

// ---------------- x2 = elu(out1 + b1) ----------------------------------------
__global__ void k_elubias1(const float* __restrict__ b) {
    int i = blockIdx.x * blockDim.x + threadIdx.x;
    if (i < NN * F1) g_x2[i] = eluf(g_out1[i] + b[i & (F1 - 1)]);
}

// ---------------- final: out = elu(out2+b2) @ Wl + bl ------------------------
__global__ void k_final(const float* __restrict__ b2, const float* __restrict__ Wl,
                        const float* __restrict__ bl, float* __restrict__ out) {
    __shared__ float sW[HIDD * NCLS];
    __shared__ float sb[NCLS];
    __shared__ float sb2[HIDD];
    int t = threadIdx.x;
    for (int i = t; i < HIDD * NCLS; i += blockDim.x) sW[i] = Wl[i];
    if (t < NCLS) sb[t] = bl[t];
    if (t < HIDD) sb2[t] = b2[t];
    __syncthreads();
    int n = blockIdx.x * blockDim.x + t;
    if (n >= NN) return;
    float acc[NCLS];
    #pragma unroll
    for (int j = 0; j < NCLS; j++) acc[j] = sb[j];
    #pragma unroll
    for (int f = 0; f < HIDD; f++) {
        float v = eluf(g_out2[(size_t)n * HIDD + f] + sb2[f]);
        #pragma unroll
        for (int j = 0; j < NCLS; j++) acc[j] += v * sW[f * NCLS + j];
    }
    #pragma unroll
    for (int j = 0; j < NCLS; j++) out[(size_t)n * NCLS + j] = acc[j];
}

// ---------------- launch ------------------------------------------------------
extern "C" void kernel_launch(void* const* d_in, const int* in_sizes, int n_in,
                              void* d_out, int out_size) {
    const float* x   = (const float*)d_in[0];
    const int*   ei  = (const int*)d_in[1];
    const float* W1  = (const float*)d_in[2];
    const float* as1 = (const float*)d_in[3];
    const float* ad1 = (const float*)d_in[4];
    const float* b1  = (const float*)d_in[5];
    const float* W2  = (const float*)d_in[6];
    const float* as2 = (const float*)d_in[7];
    const float* ad2 = (const float*)d_in[8];
    const float* b2  = (const float*)d_in[9];
    const float* Wl  = (const float*)d_in[10];
    const float* bl  = (const float*)d_in[11];
    float* out = (float*)d_out;

    const int T = 256;
    // ---- layer 1 ----
    k_init<1><<<(NN * F1 + T - 1) / T, T>>>();
    dim3 g1(F1 / 64, (NN + 63) / 64);
    k_sgemm<1><<<g1, 256>>>(x, W1);
    k_attdot<1><<<(NN * 32 + T - 1) / T, T>>>(as1, ad1);
    k_edge_ms<1, 0><<<(MM + T - 1) / T, T>>>(ei);
    k_edge_ms<1, 1><<<(MM + T - 1) / T, T>>>(ei);
    k_edge_agg<1><<<(MM * 32 + T - 1) / T, T>>>(ei);
    k_elubias1<<<(NN * F1 + T - 1) / T, T>>>(b1);
    // ---- layer 2 ----
    k_init<2><<<(NN * HIDD + T - 1) / T, T>>>();
    dim3 g2(1, (NN + 63) / 64);
    k_sgemm<2><<<g2, 256>>>(nullptr, W2);
    k_attdot<2><<<(NN * 32 + T - 1) / T, T>>>(as2, ad2);
    k_edge_ms<2, 0><<<(MM + T - 1) / T, T>>>(ei);
    k_edge_ms<2, 1><<<(MM + T - 1) / T, T>>>(ei);
    k_edge_agg<2><<<(MM * 32 + T - 1) / T, T>>>(ei);
    // ---- head ----
    k_final<<<(NN + 127) / 128, 128>>>(b2, Wl, bl, out);
}

// round 3
// speedup vs baseline: 1.8547x; 1.8547x over previous
#include <cuda_runtime.h>
#include <math.h>

#define NN   50000
#define EE   1600000
#define MM   (EE + NN)
#define IND  256
#define HIDD 64
#define NH1  2
#define F1   128        // NH1*HIDD
#define NCLS 10
#define NEG  0.2f

// ---------------- scratch (static device globals; no allocation) ------------
__device__ float g_h1[NN * F1];
__device__ float g_as1[NN * NH1], g_ad1[NN * NH1];
__device__ float g_x2[NN * F1];
__device__ float g_h2[NN * HIDD];
__device__ float g_as2[NN], g_ad2[NN];
__device__ float g_out2[NN * HIDD];     // post bias+ELU

// CSR scratch (built once per call; shared by both layers)
__device__ int g_cnt[NN];
__device__ int g_ptr[NN + 1];
__device__ int g_cur[NN];
__device__ int g_csrc[MM];

// ---------------- helpers ----------------------------------------------------
__device__ __forceinline__ float lrelu(float x) { return x > 0.f ? x : NEG * x; }
__device__ __forceinline__ float eluf(float x)  { return x > 0.f ? x : (__expf(x) - 1.f); }

// ---------------- CSR build ---------------------------------------------------
__global__ void k_initcnt() {
    int i = blockIdx.x * blockDim.x + threadIdx.x;
    if (i < NN) g_cnt[i] = 1;           // self-loop
}

__global__ void k_count(const int* __restrict__ ei) {
    int m = blockIdx.x * blockDim.x + threadIdx.x;
    if (m < EE) atomicAdd(&g_cnt[ei[EE + m]], 1);
}

// single-block exclusive scan over g_cnt -> g_ptr, g_cur
__global__ void k_scan() {
    const int T = 1024;
    const int ITEMS = (NN + 1 + T - 1) / T;   // 49
    __shared__ int sh[T];
    int t = threadIdx.x;
    int base = t * ITEMS;
    int s = 0;
    for (int k = 0; k < ITEMS; k++) {
        int i = base + k;
        if (i < NN) s += g_cnt[i];
    }
    sh[t] = s;
    __syncthreads();
    for (int off = 1; off < T; off <<= 1) {
        int v = (t >= off) ? sh[t - off] : 0;
        __syncthreads();
        sh[t] += v;
        __syncthreads();
    }
    int run = (t == 0) ? 0 : sh[t - 1];
    for (int k = 0; k < ITEMS; k++) {
        int i = base + k;
        if (i <= NN) {
            g_ptr[i] = run;
            if (i < NN) { g_cur[i] = run; run += g_cnt[i]; }
        }
    }
}

__global__ void k_scatter(const int* __restrict__ ei) {
    int m = blockIdx.x * blockDim.x + threadIdx.x;
    if (m >= MM) return;
    int s, d;
    if (m < EE) { s = ei[m]; d = ei[EE + m]; }
    else        { s = d = m - EE; }
    int pos = atomicAdd(&g_cur[d], 1);
    g_csrc[pos] = s;
}

// ---------------- tiled fp32 GEMM + fused attention-dot epilogue -------------
// C[NN,Nc] = A[NN,K] @ B[K,Nc]; BM=64 BN=64 BK=16, 4x4 microtile, 256 thr.
// Column tile == one head (64 cols), so each block fully computes
// a_s[row,head] = <C_row_tile, att_s_head>, reduced across the 16 tx lanes.
template <int L>
__global__ void k_sgemm(const float* __restrict__ Ain, const float* __restrict__ B,
                        const float* __restrict__ att_s, const float* __restrict__ att_d) {
    constexpr int K  = (L == 1) ? IND : F1;
    constexpr int Nc = (L == 1) ? F1  : HIDD;
    constexpr int H  = (L == 1) ? NH1 : 1;
    const float* A = (L == 1) ? Ain : (const float*)g_x2;
    float* C       = (L == 1) ? g_h1 : g_h2;
    float* as_     = (L == 1) ? g_as1 : g_as2;
    float* ad_     = (L == 1) ? g_ad1 : g_ad2;

    __shared__ float As[16][65];
    __shared__ float Bs[16][64];

    int tid = threadIdx.x;
    int tx = tid & 15, ty = tid >> 4;
    int row0 = blockIdx.y * 64;
    int col0 = blockIdx.x * 64;
    int head = col0 / HIDD;

    float acc[4][4] = {};
    for (int k0 = 0; k0 < K; k0 += 16) {
        #pragma unroll
        for (int i = tid; i < 64 * 16; i += 256) {
            int r = i >> 4, c = i & 15;
            int gr = row0 + r;
            As[c][r] = (gr < NN) ? A[(size_t)gr * K + k0 + c] : 0.f;
        }
        #pragma unroll
        for (int i = tid; i < 16 * 64; i += 256) {
            int r = i >> 6, c = i & 63;
            Bs[r][c] = B[(size_t)(k0 + r) * Nc + col0 + c];
        }
        __syncthreads();
        #pragma unroll
        for (int kk = 0; kk < 16; kk++) {
            float a[4], b[4];
            #pragma unroll
            for (int i = 0; i < 4; i++) a[i] = As[kk][ty * 4 + i];
            #pragma unroll
            for (int j = 0; j < 4; j++) b[j] = Bs[kk][tx * 4 + j];
            #pragma unroll
            for (int i = 0; i < 4; i++)
                #pragma unroll
                for (int j = 0; j < 4; j++) acc[i][j] += a[i] * b[j];
        }
        __syncthreads();
    }
    // store C
    #pragma unroll
    for (int i = 0; i < 4; i++) {
        int gr = row0 + ty * 4 + i;
        if (gr < NN) {
            #pragma unroll
            for (int j = 0; j < 4; j++)
                C[(size_t)gr * Nc + col0 + tx * 4 + j] = acc[i][j];
        }
    }
    // fused attention dots
    float vs[4], vd[4];
    #pragma unroll
    for (int j = 0; j < 4; j++) {
        vs[j] = att_s[col0 + tx * 4 + j];
        vd[j] = att_d[col0 + tx * 4 + j];
    }
    #pragma unroll
    for (int i = 0; i < 4; i++) {
        float ps = 0.f, pd = 0.f;
        #pragma unroll
        for (int j = 0; j < 4; j++) { ps += acc[i][j] * vs[j]; pd += acc[i][j] * vd[j]; }
        #pragma unroll
        for (int o = 8; o; o >>= 1) {
            ps += __shfl_down_sync(0xffffffffu, ps, o, 16);
            pd += __shfl_down_sync(0xffffffffu, pd, o, 16);
        }
        if (tx == 0) {
            int gr = row0 + ty * 4 + i;
            if (gr < NN) { as_[gr * H + head] = ps; ad_[gr * H + head] = pd; }
        }
    }
}

// ---------------- fused softmax + aggregation + bias + ELU (warp per node) ---
template <int L>
__global__ void k_gather(const float* __restrict__ bias) {
    constexpr int H = (L == 1) ? NH1 : 1;
    constexpr int F = H * HIDD;
    constexpr int VEC = F / 32;              // 4 (L1) or 2 (L2)
    const float* as_ = (L == 1) ? g_as1 : g_as2;
    const float* ad_ = (L == 1) ? g_ad1 : g_ad2;
    const float* h   = (L == 1) ? (const float*)g_h1 : (const float*)g_h2;
    float* outp      = (L == 1) ? g_x2 : g_out2;

    int n = (blockIdx.x * blockDim.x + threadIdx.x) >> 5;
    int lane = threadIdx.x & 31;
    if (n >= NN) return;

    int beg = g_ptr[n], end = g_ptr[n + 1];
    float ad0 = ad_[n * H];
    float ad1 = (H == 2) ? ad_[n * H + 1] : 0.f;

    float acc[VEC];
    #pragma unroll
    for (int v = 0; v < VEC; v++) acc[v] = 0.f;
    float d0 = 0.f, d1 = 0.f;

    for (int c = beg; c < end; c += 32) {
        int m = c + lane;
        int src = 0;
        float ex0 = 0.f, ex1 = 0.f;
        if (m < end) {
            src = g_csrc[m];
            ex0 = __expf(lrelu(as_[src * H] + ad0));
            if (H == 2) ex1 = __expf(lrelu(as_[src * H + 1] + ad1));
        }
        d0 += ex0; d1 += ex1;
        int cnt = min(32, end - c);
        #pragma unroll 4
        for (int j = 0; j < cnt; j++) {
            int s = __shfl_sync(0xffffffffu, src, j);
            float w0 = __shfl_sync(0xffffffffu, ex0, j);
            float w;
            if (H == 2) {
                float w1 = __shfl_sync(0xffffffffu, ex1, j);
                w = (lane < 16) ? w0 : w1;
            } else {
                w = w0;
            }
            if (VEC == 4) {
                float4 hv = *(const float4*)(h + (size_t)s * F + lane * 4);
                acc[0] += w * hv.x; acc[1] += w * hv.y;
                acc[2] += w * hv.z; acc[3] += w * hv.w;
            } else {
                float2 hv = *(const float2*)(h + (size_t)s * F + lane * 2);
                acc[0] += w * hv.x; acc[1] += w * hv.y;
            }
        }
    }
    #pragma unroll
    for (int o = 16; o; o >>= 1) {
        d0 += __shfl_xor_sync(0xffffffffu, d0, o);
        if (H == 2) d1 += __shfl_xor_sync(0xffffffffu, d1, o);
    }
    float denom = (H == 2) ? ((lane < 16) ? d0 : d1) : d0;
    float inv = 1.f / denom;

    if (VEC == 4) {
        float4 o_;
        o_.x = eluf(acc[0] * inv + bias[lane * 4 + 0]);
        o_.y = eluf(acc[1] * inv + bias[lane * 4 + 1]);
        o_.z = eluf(acc[2] * inv + bias[lane * 4 + 2]);
        o_.w = eluf(acc[3] * inv + bias[lane * 4 + 3]);
        *(float4*)(outp + (size_t)n * F + lane * 4) = o_;
    } else {
        float2 o_;
        o_.x = eluf(acc[0] * inv + bias[lane * 2 + 0]);
        o_.y = eluf(acc[1] * inv + bias[lane * 2 + 1]);
        *(float2*)(outp + (size_t)n * F + lane * 2) = o_;
    }
}

// ---------------- final head: out = g_out2 @ Wl + bl -------------------------
__global__ void k_final(const float* __restrict__ Wl, const float* __restrict__ bl,
                        float* __restrict__ out) {
    __shared__ float sW[HIDD * NCLS];
    __shared__ float sb[NCLS];
    int t = threadIdx.x;
    for (int i = t; i < HIDD * NCLS; i += blockDim.x) sW[i] = Wl[i];
    if (t < NCLS) sb[t] = bl[t];
    __syncthreads();
    int n = blockIdx.x * blockDim.x + t;
    if (n >= NN) return;
    float acc[NCLS];
    #pragma unroll
    for (int j = 0; j < NCLS; j++) acc[j] = sb[j];
    #pragma unroll
    for (int f = 0; f < HIDD; f++) {
        float v = g_out2[(size_t)n * HIDD + f];
        #pragma unroll
        for (int j = 0; j < NCLS; j++) acc[j] += v * sW[f * NCLS + j];
    }
    #pragma unroll
    for (int j = 0; j < NCLS; j++) out[(size_t)n * NCLS + j] = acc[j];
}

// ---------------- launch ------------------------------------------------------
extern "C" void kernel_launch(void* const* d_in, const int* in_sizes, int n_in,
                              void* d_out, int out_size) {
    const float* x   = (const float*)d_in[0];
    const int*   ei  = (const int*)d_in[1];
    const float* W1  = (const float*)d_in[2];
    const float* as1 = (const float*)d_in[3];
    const float* ad1 = (const float*)d_in[4];
    const float* b1  = (const float*)d_in[5];
    const float* W2  = (const float*)d_in[6];
    const float* as2 = (const float*)d_in[7];
    const float* ad2 = (const float*)d_in[8];
    const float* b2  = (const float*)d_in[9];
    const float* Wl  = (const float*)d_in[10];
    const float* bl  = (const float*)d_in[11];
    float* out = (float*)d_out;

    const int T = 256;
    // ---- CSR build (shared by both layers) ----
    k_initcnt<<<(NN + T - 1) / T, T>>>();
    k_count<<<(EE + T - 1) / T, T>>>(ei);
    k_scan<<<1, 1024>>>();
    k_scatter<<<(MM + T - 1) / T, T>>>(ei);
    // ---- layer 1 ----
    k_sgemm<1><<<dim3(F1 / 64, (NN + 63) / 64), 256>>>(x, W1, as1, ad1);
    k_gather<1><<<(NN + 7) / 8, 256>>>(b1);
    // ---- layer 2 ----
    k_sgemm<2><<<dim3(1, (NN + 63) / 64), 256>>>(nullptr, W2, as2, ad2);
    k_gather<2><<<(NN + 7) / 8, 256>>>(b2);
    // ---- head ----
    k_final<<<(NN + 127) / 128, 128>>>(Wl, bl, out);
}

// round 4
// speedup vs baseline: 2.2156x; 1.1946x over previous
#include <cuda_runtime.h>
#include <math.h>

#define NN   50000
#define EE   1600000
#define MM   (EE + NN)
#define IND  256
#define HIDD 64
#define NH1  2
#define F1   128        // NH1*HIDD
#define NCLS 10
#define NEG  0.2f

// ---------------- scratch (static device globals; no allocation) ------------
__device__ float g_h1[NN * F1];
__device__ float g_as1[NN * NH1], g_ad1[NN * NH1];
__device__ float g_x2[NN * F1];
__device__ float g_h2[NN * HIDD];
__device__ float g_as2[NN], g_ad2[NN];

// CSR scratch (built once per call; shared by both layers)
__device__ int g_cnt[NN];
__device__ int g_ptr[NN + 1];
__device__ int g_cur[NN];
__device__ int g_csrc[MM];

// ---------------- helpers ----------------------------------------------------
__device__ __forceinline__ float lrelu(float x) { return x > 0.f ? x : NEG * x; }
__device__ __forceinline__ float eluf(float x)  { return x > 0.f ? x : (__expf(x) - 1.f); }

union F2U { float2 f; unsigned long long u; };
// packed dual fp32 FMA: d.lo += a.lo*b.lo ; d.hi += a.hi*b.hi  (sm_103a)
__device__ __forceinline__ void ffma2(F2U& d, const F2U& a, const F2U& b) {
    asm("fma.rn.f32x2 %0, %1, %2, %0;" : "+l"(d.u) : "l"(a.u), "l"(b.u));
}

// ---------------- CSR build ---------------------------------------------------
__global__ void k_initcnt() {
    int i = blockIdx.x * blockDim.x + threadIdx.x;
    if (i < NN) g_cnt[i] = 1;           // self-loop
}

__global__ void k_count(const int* __restrict__ ei) {
    int m4 = blockIdx.x * blockDim.x + threadIdx.x;
    if (m4 < EE / 4) {
        int4 d = ((const int4*)(ei + EE))[m4];
        atomicAdd(&g_cnt[d.x], 1);
        atomicAdd(&g_cnt[d.y], 1);
        atomicAdd(&g_cnt[d.z], 1);
        atomicAdd(&g_cnt[d.w], 1);
    }
}

// single-block exclusive scan over g_cnt -> g_ptr, g_cur
__global__ void k_scan() {
    const int T = 1024;
    const int ITEMS = (NN + 1 + T - 1) / T;   // 49
    __shared__ int sh[T];
    int t = threadIdx.x;
    int base = t * ITEMS;
    int s = 0;
    for (int k = 0; k < ITEMS; k++) {
        int i = base + k;
        if (i < NN) s += g_cnt[i];
    }
    sh[t] = s;
    __syncthreads();
    for (int off = 1; off < T; off <<= 1) {
        int v = (t >= off) ? sh[t - off] : 0;
        __syncthreads();
        sh[t] += v;
        __syncthreads();
    }
    int run = (t == 0) ? 0 : sh[t - 1];
    for (int k = 0; k < ITEMS; k++) {
        int i = base + k;
        if (i <= NN) {
            g_ptr[i] = run;
            if (i < NN) { g_cur[i] = run; run += g_cnt[i]; }
        }
    }
}

__global__ void k_scatter(const int* __restrict__ ei) {
    int m4 = blockIdx.x * blockDim.x + threadIdx.x;
    if (m4 < EE / 4) {
        int4 s = ((const int4*)ei)[m4];
        int4 d = ((const int4*)(ei + EE))[m4];
        g_csrc[atomicAdd(&g_cur[d.x], 1)] = s.x;
        g_csrc[atomicAdd(&g_cur[d.y], 1)] = s.y;
        g_csrc[atomicAdd(&g_cur[d.z], 1)] = s.z;
        g_csrc[atomicAdd(&g_cur[d.w], 1)] = s.w;
    } else {
        int n = m4 - EE / 4;
        if (n < NN) g_csrc[atomicAdd(&g_cur[n], 1)] = n;  // self-loop
    }
}

// ---------------- f32x2 GEMM + fused attention-dot epilogue ------------------
// C[NN,Nc] = A[NN,K] @ B[K,Nc]; BM=128, BN=Nc, BK=16, 256 threads.
// Microtile 8 rows x TN cols per thread; accumulators packed as f32x2 over
// row pairs (A pairs come free from LDS.128; B value duplicated per pair).
template <int L>
__global__ void __launch_bounds__(256) k_sgemm(
        const float* __restrict__ Ain, const float* __restrict__ B,
        const float* __restrict__ att_s, const float* __restrict__ att_d) {
    constexpr int K  = (L == 1) ? IND : F1;
    constexpr int Nc = (L == 1) ? F1  : HIDD;
    constexpr int H  = (L == 1) ? NH1 : 1;
    constexpr int TN = Nc / 16;           // 8 (L1) / 4 (L2)
    constexpr int NT = K / 16;            // k-tiles
    constexpr int BV = (16 * Nc / 4) / 256;  // B float4s per thread: 2 / 1
    const float* A = (L == 1) ? Ain : (const float*)g_x2;
    float* C   = (L == 1) ? g_h1 : g_h2;
    float* as_ = (L == 1) ? g_as1 : g_as2;
    float* ad_ = (L == 1) ? g_ad1 : g_ad2;

    __shared__ float As[16 * 128];   // transposed: As[k][row]
    __shared__ float Bs[16 * Nc];    // row-major:  Bs[k][col]

    int tid = threadIdx.x;
    int tx = tid & 15, ty = tid >> 4;
    int lane = tid & 31;
    int row0 = blockIdx.y * 128;

    float4 pa[2], pb[2];

    auto loadA = [&](int t) {
        int k0 = t * 16;
        #pragma unroll
        for (int p = 0; p < 2; p++) {
            int idx = tid + p * 256;
            int r = idx >> 2, c4 = idx & 3;
            int gr = row0 + r;
            pa[p] = (gr < NN) ? *(const float4*)&A[(size_t)gr * K + k0 + c4 * 4]
                              : make_float4(0.f, 0.f, 0.f, 0.f);
        }
    };
    auto loadB = [&](int t) {
        int k0 = t * 16;
        #pragma unroll
        for (int p = 0; p < BV; p++) {
            int idx = tid + p * 256;
            int r = idx / (Nc / 4), c4 = idx % (Nc / 4);
            pb[p] = *(const float4*)&B[(size_t)(k0 + r) * Nc + c4 * 4];
        }
    };
    auto stageA = [&]() {
        #pragma unroll
        for (int p = 0; p < 2; p++) {
            int idx = tid + p * 256;
            int r = idx >> 2, c4 = idx & 3;
            As[(c4 * 4 + 0) * 128 + r] = pa[p].x;
            As[(c4 * 4 + 1) * 128 + r] = pa[p].y;
            As[(c4 * 4 + 2) * 128 + r] = pa[p].z;
            As[(c4 * 4 + 3) * 128 + r] = pa[p].w;
        }
    };
    auto stageB = [&]() {
        #pragma unroll
        for (int p = 0; p < BV; p++) {
            int idx = tid + p * 256;
            int r = idx / (Nc / 4), c4 = idx % (Nc / 4);
            *(float4*)&Bs[r * Nc + c4 * 4] = pb[p];
        }
    };

    F2U acc[4][TN];
    #pragma unroll
    for (int i = 0; i < 4; i++)
        #pragma unroll
        for (int j = 0; j < TN; j++) acc[i][j].f = make_float2(0.f, 0.f);

    loadA(0); loadB(0);
    stageA(); stageB();
    __syncthreads();

    for (int t = 0; t < NT; t++) {
        if (t + 1 < NT) { loadA(t + 1); loadB(t + 1); }
        #pragma unroll
        for (int kk = 0; kk < 16; kk++) {
            ulonglong2 av0 = *(const ulonglong2*)&As[kk * 128 + ty * 8];
            ulonglong2 av1 = *(const ulonglong2*)&As[kk * 128 + ty * 8 + 4];
            F2U ap[4];
            ap[0].u = av0.x; ap[1].u = av0.y; ap[2].u = av1.x; ap[3].u = av1.y;
            float bv[TN];
            #pragma unroll
            for (int q = 0; q < TN / 4; q++)
                *(float4*)&bv[q * 4] = *(const float4*)&Bs[kk * Nc + tx * TN + q * 4];
            #pragma unroll
            for (int j = 0; j < TN; j++) {
                F2U bb; bb.f = make_float2(bv[j], bv[j]);
                #pragma unroll
                for (int i2 = 0; i2 < 4; i2++) ffma2(acc[i2][j], ap[i2], bb);
            }
        }
        __syncthreads();
        if (t + 1 < NT) { stageA(); stageB(); __syncthreads(); }
    }

    // store C (two rows per acc pair)
    #pragma unroll
    for (int i2 = 0; i2 < 4; i2++) {
        #pragma unroll
        for (int p = 0; p < 2; p++) {
            int gr = row0 + ty * 8 + 2 * i2 + p;
            if (gr < NN) {
                #pragma unroll
                for (int q = 0; q < TN / 4; q++) {
                    float4 v;
                    v.x = p ? acc[i2][q * 4 + 0].f.y : acc[i2][q * 4 + 0].f.x;
                    v.y = p ? acc[i2][q * 4 + 1].f.y : acc[i2][q * 4 + 1].f.x;
                    v.z = p ? acc[i2][q * 4 + 2].f.y : acc[i2][q * 4 + 2].f.x;
                    v.w = p ? acc[i2][q * 4 + 3].f.y : acc[i2][q * 4 + 3].f.x;
                    *(float4*)&C[(size_t)gr * Nc + tx * TN + q * 4] = v;
                }
            }
        }
    }

    // fused attention dots: reduce across tx lanes owning this head's columns
    constexpr int W = (L == 1) ? 8 : 16;   // lanes per head group
    float vs[TN], vd[TN];
    #pragma unroll
    for (int j = 0; j < TN; j++) {
        vs[j] = att_s[tx * TN + j];
        vd[j] = att_d[tx * TN + j];
    }
    #pragma unroll
    for (int i2 = 0; i2 < 4; i2++) {
        #pragma unroll
        for (int p = 0; p < 2; p++) {
            float ps = 0.f, pd = 0.f;
            #pragma unroll
            for (int j = 0; j < TN; j++) {
                float av = p ? acc[i2][j].f.y : acc[i2][j].f.x;
                ps += av * vs[j];
                pd += av * vd[j];
            }
            #pragma unroll
            for (int o = W / 2; o; o >>= 1) {
                ps += __shfl_down_sync(0xffffffffu, ps, o, W);
                pd += __shfl_down_sync(0xffffffffu, pd, o, W);
            }
            if ((lane % W) == 0) {
                int gr = row0 + ty * 8 + 2 * i2 + p;
                int head = (L == 1) ? (tx >> 3) : 0;
                if (gr < NN) { as_[gr * H + head] = ps; ad_[gr * H + head] = pd; }
            }
        }
    }
}

// ---------------- fused softmax + aggregation + bias + ELU (warp per node) ---
// L==2 additionally fuses the classifier head: out = elu(agg+b2) @ Wl + bl.
template <int L>
__global__ void k_gather(const float* __restrict__ bias,
                         const float* __restrict__ Wl, const float* __restrict__ bl,
                         float* __restrict__ out) {
    constexpr int H = (L == 1) ? NH1 : 1;
    constexpr int F = H * HIDD;
    constexpr int VEC = F / 32;              // 4 (L1) or 2 (L2)
    const float* as_ = (L == 1) ? g_as1 : g_as2;
    const float* ad_ = (L == 1) ? g_ad1 : g_ad2;
    const float* h   = (L == 1) ? (const float*)g_h1 : (const float*)g_h2;

    int n = (blockIdx.x * blockDim.x + threadIdx.x) >> 5;
    int lane = threadIdx.x & 31;
    if (n >= NN) return;

    int beg = g_ptr[n], end = g_ptr[n + 1];
    float ad0 = ad_[n * H];
    float ad1 = (H == 2) ? ad_[n * H + 1] : 0.f;

    float acc[VEC];
    #pragma unroll
    for (int v = 0; v < VEC; v++) acc[v] = 0.f;
    float d0 = 0.f, d1 = 0.f;

    for (int c = beg; c < end; c += 32) {
        int m = c + lane;
        int src = 0;
        float ex0 = 0.f, ex1 = 0.f;
        if (m < end) {
            src = g_csrc[m];
            ex0 = __expf(lrelu(as_[src * H] + ad0));
            if (H == 2) ex1 = __expf(lrelu(as_[src * H + 1] + ad1));
        }
        d0 += ex0; d1 += ex1;
        int cnt = min(32, end - c);
        #pragma unroll 4
        for (int j = 0; j < cnt; j++) {
            int s = __shfl_sync(0xffffffffu, src, j);
            float w0 = __shfl_sync(0xffffffffu, ex0, j);
            float w;
            if (H == 2) {
                float w1 = __shfl_sync(0xffffffffu, ex1, j);
                w = (lane < 16) ? w0 : w1;
            } else {
                w = w0;
            }
            if (VEC == 4) {
                float4 hv = *(const float4*)(h + (size_t)s * F + lane * 4);
                acc[0] += w * hv.x; acc[1] += w * hv.y;
                acc[2] += w * hv.z; acc[3] += w * hv.w;
            } else {
                float2 hv = *(const float2*)(h + (size_t)s * F + lane * 2);
                acc[0] += w * hv.x; acc[1] += w * hv.y;
            }
        }
    }
    #pragma unroll
    for (int o = 16; o; o >>= 1) {
        d0 += __shfl_xor_sync(0xffffffffu, d0, o);
        if (H == 2) d1 += __shfl_xor_sync(0xffffffffu, d1, o);
    }
    float denom = (H == 2) ? ((lane < 16) ? d0 : d1) : d0;
    float inv = 1.f / denom;

    if (L == 1) {
        float4 o_;
        o_.x = eluf(acc[0] * inv + bias[lane * 4 + 0]);
        o_.y = eluf(acc[1] * inv + bias[lane * 4 + 1]);
        o_.z = eluf(acc[2] * inv + bias[lane * 4 + 2]);
        o_.w = eluf(acc[3] * inv + bias[lane * 4 + 3]);
        *(float4*)(g_x2 + (size_t)n * F + lane * 4) = o_;
    } else {
        float v0 = eluf(acc[0] * inv + bias[lane * 2 + 0]);
        float v1 = eluf(acc[1] * inv + bias[lane * 2 + 1]);
        int f0 = lane * 2, f1 = lane * 2 + 1;
        float cls[NCLS];
        #pragma unroll
        for (int j = 0; j < NCLS; j++)
            cls[j] = v0 * Wl[f0 * NCLS + j] + v1 * Wl[f1 * NCLS + j];
        #pragma unroll
        for (int o = 16; o; o >>= 1)
            #pragma unroll
            for (int j = 0; j < NCLS; j++)
                cls[j] += __shfl_xor_sync(0xffffffffu, cls[j], o);
        if (lane == 0) {
            #pragma unroll
            for (int j = 0; j < NCLS; j++)
                out[(size_t)n * NCLS + j] = cls[j] + bl[j];
        }
    }
}

// ---------------- launch ------------------------------------------------------
extern "C" void kernel_launch(void* const* d_in, const int* in_sizes, int n_in,
                              void* d_out, int out_size) {
    const float* x   = (const float*)d_in[0];
    const int*   ei  = (const int*)d_in[1];
    const float* W1  = (const float*)d_in[2];
    const float* as1 = (const float*)d_in[3];
    const float* ad1 = (const float*)d_in[4];
    const float* b1  = (const float*)d_in[5];
    const float* W2  = (const float*)d_in[6];
    const float* as2 = (const float*)d_in[7];
    const float* ad2 = (const float*)d_in[8];
    const float* b2  = (const float*)d_in[9];
    const float* Wl  = (const float*)d_in[10];
    const float* bl  = (const float*)d_in[11];
    float* out = (float*)d_out;

    const int T = 256;
    // ---- CSR build (shared by both layers) ----
    k_initcnt<<<(NN + T - 1) / T, T>>>();
    k_count<<<(EE / 4 + T - 1) / T, T>>>(ei);
    k_scan<<<1, 1024>>>();
    k_scatter<<<(EE / 4 + NN + T - 1) / T, T>>>(ei);
    // ---- layer 1 ----
    k_sgemm<1><<<dim3(1, (NN + 127) / 128), 256>>>(x, W1, as1, ad1);
    k_gather<1><<<(NN + 7) / 8, 256>>>(b1, nullptr, nullptr, nullptr);
    // ---- layer 2 (classifier head fused into gather) ----
    k_sgemm<2><<<dim3(1, (NN + 127) / 128), 256>>>(nullptr, W2, as2, ad2);
    k_gather<2><<<(NN + 7) / 8, 256>>>(b2, Wl, bl, out);
}

// round 5
// speedup vs baseline: 2.9386x; 1.3264x over previous
#include <cuda_runtime.h>
#include <math.h>

#define NN   50000
#define EE   1600000
#define MM   (EE + NN)
#define IND  256
#define HIDD 64
#define NH1  2
#define F1   128        // NH1*HIDD
#define NCLS 10
#define NEG  0.2f

#define SCAN_B 196      // ceil(NN/256)

// ---------------- scratch (static device globals; no allocation) ------------
__device__ float g_h1[NN * F1];
__device__ float g_as1[NN * NH1], g_ad1[NN * NH1];
__device__ float g_x2[NN * F1];
__device__ float g_h2[NN * HIDD];
__device__ float g_as2[NN], g_ad2[NN];

// CSR scratch (built once per call; shared by both layers)
__device__ int g_cnt[NN];
__device__ int g_part[SCAN_B];
__device__ int g_off[SCAN_B];
__device__ int g_ptr[NN + 1];
__device__ int g_cur[NN];
__device__ int g_csrc[MM];

// ---------------- helpers ----------------------------------------------------
__device__ __forceinline__ float lrelu(float x) { return x > 0.f ? x : NEG * x; }
__device__ __forceinline__ float eluf(float x)  { return x > 0.f ? x : (__expf(x) - 1.f); }

union F2U { float2 f; unsigned long long u; };
// packed dual fp32 FMA: d.lo += a.lo*b.lo ; d.hi += a.hi*b.hi  (sm_103a)
__device__ __forceinline__ void ffma2(F2U& d, const F2U& a, const F2U& b) {
    asm("fma.rn.f32x2 %0, %1, %2, %0;" : "+l"(d.u) : "l"(a.u), "l"(b.u));
}

// ---------------- CSR build ---------------------------------------------------
__global__ void k_count(const int* __restrict__ ei) {
    int m4 = blockIdx.x * blockDim.x + threadIdx.x;
    if (m4 < EE / 4) {
        int4 d = ((const int4*)(ei + EE))[m4];
        atomicAdd(&g_cnt[d.x], 1);
        atomicAdd(&g_cnt[d.y], 1);
        atomicAdd(&g_cnt[d.z], 1);
        atomicAdd(&g_cnt[d.w], 1);
    }
}

// phase 1: per-block sums of (cnt[i]+1)  [+1 folds in the self-loop]
__global__ void k_scan1() {
    __shared__ int sw[8];
    int i = blockIdx.x * 256 + threadIdx.x;
    int v = (i < NN) ? (g_cnt[i] + 1) : 0;
    int s = v;
    #pragma unroll
    for (int o = 16; o; o >>= 1) s += __shfl_xor_sync(0xffffffffu, s, o);
    if ((threadIdx.x & 31) == 0) sw[threadIdx.x >> 5] = s;
    __syncthreads();
    if (threadIdx.x == 0) {
        int t = 0;
        #pragma unroll
        for (int w = 0; w < 8; w++) t += sw[w];
        g_part[blockIdx.x] = t;
    }
}

// phase 2: single-block exclusive scan of SCAN_B partials
__global__ void k_scan2() {
    __shared__ int sh[256];
    int t = threadIdx.x;
    int v = (t < SCAN_B) ? g_part[t] : 0;
    sh[t] = v;
    __syncthreads();
    for (int off = 1; off < 256; off <<= 1) {
        int u = (t >= off) ? sh[t - off] : 0;
        __syncthreads();
        sh[t] += u;
        __syncthreads();
    }
    if (t < SCAN_B) g_off[t] = sh[t] - v;       // exclusive
    if (t == 255) g_ptr[NN] = sh[255];          // total = MM
}

// phase 3: in-block exclusive scan + global offset; write ptr & cur
__global__ void k_scan3() {
    __shared__ int sw[8];
    int t = threadIdx.x;
    int i = blockIdx.x * 256 + t;
    int v = (i < NN) ? (g_cnt[i] + 1) : 0;
    int lane = t & 31, w = t >> 5;
    // warp inclusive scan
    int s = v;
    #pragma unroll
    for (int o = 1; o < 32; o <<= 1) {
        int u = __shfl_up_sync(0xffffffffu, s, o);
        if (lane >= o) s += u;
    }
    if (lane == 31) sw[w] = s;
    __syncthreads();
    if (t < 8) {
        int u = sw[t];
        #pragma unroll
        for (int o = 1; o < 8; o <<= 1) {
            int uu = __shfl_up_sync(0xffu, u, o);
            if (t >= o) u += uu;
        }
        sw[t] = u;
    }
    __syncthreads();
    int excl = s - v + (w ? sw[w - 1] : 0) + g_off[blockIdx.x];
    if (i < NN) { g_ptr[i] = excl; g_cur[i] = excl; }
}

__global__ void k_scatter(const int* __restrict__ ei) {
    int m4 = blockIdx.x * blockDim.x + threadIdx.x;
    if (m4 < EE / 4) {
        int4 s = ((const int4*)ei)[m4];
        int4 d = ((const int4*)(ei + EE))[m4];
        g_csrc[atomicAdd(&g_cur[d.x], 1)] = s.x;
        g_csrc[atomicAdd(&g_cur[d.y], 1)] = s.y;
        g_csrc[atomicAdd(&g_cur[d.z], 1)] = s.z;
        g_csrc[atomicAdd(&g_cur[d.w], 1)] = s.w;
    } else {
        int n = m4 - EE / 4;
        if (n < NN) g_csrc[atomicAdd(&g_cur[n], 1)] = n;  // self-loop
    }
}

// ---------------- f32x2 GEMM + fused attention-dot epilogue ------------------
// C[NN,Nc] = A[NN,K] @ B[K,Nc]; BM=128, BN=Nc, BK=16, 256 threads.
template <int L>
__global__ void __launch_bounds__(256) k_sgemm(
        const float* __restrict__ Ain, const float* __restrict__ B,
        const float* __restrict__ att_s, const float* __restrict__ att_d) {
    constexpr int K  = (L == 1) ? IND : F1;
    constexpr int Nc = (L == 1) ? F1  : HIDD;
    constexpr int H  = (L == 1) ? NH1 : 1;
    constexpr int TN = Nc / 16;           // 8 (L1) / 4 (L2)
    constexpr int NT = K / 16;            // k-tiles
    constexpr int BV = (16 * Nc / 4) / 256;  // B float4s per thread: 2 / 1
    const float* A = (L == 1) ? Ain : (const float*)g_x2;
    float* C   = (L == 1) ? g_h1 : g_h2;
    float* as_ = (L == 1) ? g_as1 : g_as2;
    float* ad_ = (L == 1) ? g_ad1 : g_ad2;

    __shared__ float As[16 * 128];   // transposed: As[k][row]
    __shared__ float Bs[16 * Nc];    // row-major:  Bs[k][col]

    int tid = threadIdx.x;
    int tx = tid & 15, ty = tid >> 4;
    int lane = tid & 31;
    int row0 = blockIdx.y * 128;

    float4 pa[2], pb[2];

    auto loadA = [&](int t) {
        int k0 = t * 16;
        #pragma unroll
        for (int p = 0; p < 2; p++) {
            int idx = tid + p * 256;
            int r = idx >> 2, c4 = idx & 3;
            int gr = row0 + r;
            pa[p] = (gr < NN) ? *(const float4*)&A[(size_t)gr * K + k0 + c4 * 4]
                              : make_float4(0.f, 0.f, 0.f, 0.f);
        }
    };
    auto loadB = [&](int t) {
        int k0 = t * 16;
        #pragma unroll
        for (int p = 0; p < BV; p++) {
            int idx = tid + p * 256;
            int r = idx / (Nc / 4), c4 = idx % (Nc / 4);
            pb[p] = *(const float4*)&B[(size_t)(k0 + r) * Nc + c4 * 4];
        }
    };
    auto stageA = [&]() {
        #pragma unroll
        for (int p = 0; p < 2; p++) {
            int idx = tid + p * 256;
            int r = idx >> 2, c4 = idx & 3;
            As[(c4 * 4 + 0) * 128 + r] = pa[p].x;
            As[(c4 * 4 + 1) * 128 + r] = pa[p].y;
            As[(c4 * 4 + 2) * 128 + r] = pa[p].z;
            As[(c4 * 4 + 3) * 128 + r] = pa[p].w;
        }
    };
    auto stageB = [&]() {
        #pragma unroll
        for (int p = 0; p < BV; p++) {
            int idx = tid + p * 256;
            int r = idx / (Nc / 4), c4 = idx % (Nc / 4);
            *(float4*)&Bs[r * Nc + c4 * 4] = pb[p];
        }
    };

    F2U acc[4][TN];
    #pragma unroll
    for (int i = 0; i < 4; i++)
        #pragma unroll
        for (int j = 0; j < TN; j++) acc[i][j].f = make_float2(0.f, 0.f);

    loadA(0); loadB(0);
    stageA(); stageB();
    __syncthreads();

    for (int t = 0; t < NT; t++) {
        if (t + 1 < NT) { loadA(t + 1); loadB(t + 1); }
        #pragma unroll
        for (int kk = 0; kk < 16; kk++) {
            ulonglong2 av0 = *(const ulonglong2*)&As[kk * 128 + ty * 8];
            ulonglong2 av1 = *(const ulonglong2*)&As[kk * 128 + ty * 8 + 4];
            F2U ap[4];
            ap[0].u = av0.x; ap[1].u = av0.y; ap[2].u = av1.x; ap[3].u = av1.y;
            float bv[TN];
            #pragma unroll
            for (int q = 0; q < TN / 4; q++)
                *(float4*)&bv[q * 4] = *(const float4*)&Bs[kk * Nc + tx * TN + q * 4];
            #pragma unroll
            for (int j = 0; j < TN; j++) {
                F2U bb; bb.f = make_float2(bv[j], bv[j]);
                #pragma unroll
                for (int i2 = 0; i2 < 4; i2++) ffma2(acc[i2][j], ap[i2], bb);
            }
        }
        __syncthreads();
        if (t + 1 < NT) { stageA(); stageB(); __syncthreads(); }
    }

    // store C (two rows per acc pair)
    #pragma unroll
    for (int i2 = 0; i2 < 4; i2++) {
        #pragma unroll
        for (int p = 0; p < 2; p++) {
            int gr = row0 + ty * 8 + 2 * i2 + p;
            if (gr < NN) {
                #pragma unroll
                for (int q = 0; q < TN / 4; q++) {
                    float4 v;
                    v.x = p ? acc[i2][q * 4 + 0].f.y : acc[i2][q * 4 + 0].f.x;
                    v.y = p ? acc[i2][q * 4 + 1].f.y : acc[i2][q * 4 + 1].f.x;
                    v.z = p ? acc[i2][q * 4 + 2].f.y : acc[i2][q * 4 + 2].f.x;
                    v.w = p ? acc[i2][q * 4 + 3].f.y : acc[i2][q * 4 + 3].f.x;
                    *(float4*)&C[(size_t)gr * Nc + tx * TN + q * 4] = v;
                }
            }
        }
    }

    // fused attention dots
    constexpr int W = (L == 1) ? 8 : 16;   // lanes per head group
    float vs[TN], vd[TN];
    #pragma unroll
    for (int j = 0; j < TN; j++) {
        vs[j] = att_s[tx * TN + j];
        vd[j] = att_d[tx * TN + j];
    }
    #pragma unroll
    for (int i2 = 0; i2 < 4; i2++) {
        #pragma unroll
        for (int p = 0; p < 2; p++) {
            float ps = 0.f, pd = 0.f;
            #pragma unroll
            for (int j = 0; j < TN; j++) {
                float av = p ? acc[i2][j].f.y : acc[i2][j].f.x;
                ps += av * vs[j];
                pd += av * vd[j];
            }
            #pragma unroll
            for (int o = W / 2; o; o >>= 1) {
                ps += __shfl_down_sync(0xffffffffu, ps, o, W);
                pd += __shfl_down_sync(0xffffffffu, pd, o, W);
            }
            if ((lane % W) == 0) {
                int gr = row0 + ty * 8 + 2 * i2 + p;
                int head = (L == 1) ? (tx >> 3) : 0;
                if (gr < NN) { as_[gr * H + head] = ps; ad_[gr * H + head] = pd; }
            }
        }
    }
}

// ---------------- fused softmax + aggregation + bias + ELU (warp per node) ---
// L==2 additionally fuses the classifier head: out = elu(agg+b2) @ Wl + bl.
template <int L>
__global__ void k_gather(const float* __restrict__ bias,
                         const float* __restrict__ Wl, const float* __restrict__ bl,
                         float* __restrict__ out) {
    constexpr int H = (L == 1) ? NH1 : 1;
    constexpr int F = H * HIDD;
    constexpr int VEC = F / 32;              // 4 (L1) or 2 (L2)
    const float* as_ = (L == 1) ? g_as1 : g_as2;
    const float* ad_ = (L == 1) ? g_ad1 : g_ad2;
    const float* h   = (L == 1) ? (const float*)g_h1 : (const float*)g_h2;

    int n = (blockIdx.x * blockDim.x + threadIdx.x) >> 5;
    int lane = threadIdx.x & 31;
    if (n >= NN) return;

    int beg = g_ptr[n], end = g_ptr[n + 1];
    float ad0 = ad_[n * H];
    float ad1 = (H == 2) ? ad_[n * H + 1] : 0.f;

    float acc[VEC];
    #pragma unroll
    for (int v = 0; v < VEC; v++) acc[v] = 0.f;
    float d0 = 0.f, d1 = 0.f;

    for (int c = beg; c < end; c += 32) {
        int m = c + lane;
        int src = 0;
        float ex0 = 0.f, ex1 = 0.f;
        if (m < end) {
            src = g_csrc[m];
            ex0 = __expf(lrelu(as_[src * H] + ad0));
            if (H == 2) ex1 = __expf(lrelu(as_[src * H + 1] + ad1));
        }
        d0 += ex0; d1 += ex1;
        int cnt = min(32, end - c);
        #pragma unroll 4
        for (int j = 0; j < cnt; j++) {
            int s = __shfl_sync(0xffffffffu, src, j);
            float w0 = __shfl_sync(0xffffffffu, ex0, j);
            float w;
            if (H == 2) {
                float w1 = __shfl_sync(0xffffffffu, ex1, j);
                w = (lane < 16) ? w0 : w1;
            } else {
                w = w0;
            }
            if (VEC == 4) {
                float4 hv = *(const float4*)(h + (size_t)s * F + lane * 4);
                acc[0] += w * hv.x; acc[1] += w * hv.y;
                acc[2] += w * hv.z; acc[3] += w * hv.w;
            } else {
                float2 hv = *(const float2*)(h + (size_t)s * F + lane * 2);
                acc[0] += w * hv.x; acc[1] += w * hv.y;
            }
        }
    }
    #pragma unroll
    for (int o = 16; o; o >>= 1) {
        d0 += __shfl_xor_sync(0xffffffffu, d0, o);
        if (H == 2) d1 += __shfl_xor_sync(0xffffffffu, d1, o);
    }
    float denom = (H == 2) ? ((lane < 16) ? d0 : d1) : d0;
    float inv = 1.f / denom;

    if (L == 1) {
        float4 o_;
        o_.x = eluf(acc[0] * inv + bias[lane * 4 + 0]);
        o_.y = eluf(acc[1] * inv + bias[lane * 4 + 1]);
        o_.z = eluf(acc[2] * inv + bias[lane * 4 + 2]);
        o_.w = eluf(acc[3] * inv + bias[lane * 4 + 3]);
        *(float4*)(g_x2 + (size_t)n * F + lane * 4) = o_;
    } else {
        float v0 = eluf(acc[0] * inv + bias[lane * 2 + 0]);
        float v1 = eluf(acc[1] * inv + bias[lane * 2 + 1]);
        int f0 = lane * 2, f1 = lane * 2 + 1;
        float cls[NCLS];
        #pragma unroll
        for (int j = 0; j < NCLS; j++)
            cls[j] = v0 * Wl[f0 * NCLS + j] + v1 * Wl[f1 * NCLS + j];
        #pragma unroll
        for (int o = 16; o; o >>= 1)
            #pragma unroll
            for (int j = 0; j < NCLS; j++)
                cls[j] += __shfl_xor_sync(0xffffffffu, cls[j], o);
        if (lane == 0) {
            #pragma unroll
            for (int j = 0; j < NCLS; j++)
                out[(size_t)n * NCLS + j] = cls[j] + bl[j];
        }
    }
}

// ---------------- launch ------------------------------------------------------
extern "C" void kernel_launch(void* const* d_in, const int* in_sizes, int n_in,
                              void* d_out, int out_size) {
    const float* x   = (const float*)d_in[0];
    const int*   ei  = (const int*)d_in[1];
    const float* W1  = (const float*)d_in[2];
    const float* as1 = (const float*)d_in[3];
    const float* ad1 = (const float*)d_in[4];
    const float* b1  = (const float*)d_in[5];
    const float* W2  = (const float*)d_in[6];
    const float* as2 = (const float*)d_in[7];
    const float* ad2 = (const float*)d_in[8];
    const float* b2  = (const float*)d_in[9];
    const float* Wl  = (const float*)d_in[10];
    const float* bl  = (const float*)d_in[11];
    float* out = (float*)d_out;

    // one-time infra (created on the eager correctness call, reused thereafter;
    // no device memory is allocated)
    static cudaStream_t s2 = nullptr;
    static cudaEvent_t e0 = nullptr, e1 = nullptr;
    static void* cnt_addr = nullptr;
    if (!s2) {
        cudaStreamCreateWithFlags(&s2, cudaStreamNonBlocking);
        cudaEventCreateWithFlags(&e0, cudaEventDisableTiming);
        cudaEventCreateWithFlags(&e1, cudaEventDisableTiming);
        cudaGetSymbolAddress(&cnt_addr, g_cnt);
    }

    const int T = 256;
    // ---- fork: CSR build on side stream, GEMM1 on main stream ----
    cudaEventRecord(e0, 0);
    cudaStreamWaitEvent(s2, e0, 0);
    cudaMemsetAsync(cnt_addr, 0, NN * sizeof(int), s2);
    k_count<<<(EE / 4 + T - 1) / T, T, 0, s2>>>(ei);
    k_scan1<<<SCAN_B, 256, 0, s2>>>();
    k_scan2<<<1, 256, 0, s2>>>();
    k_scan3<<<SCAN_B, 256, 0, s2>>>();
    k_scatter<<<(EE / 4 + NN + T - 1) / T, T, 0, s2>>>(ei);
    cudaEventRecord(e1, s2);

    k_sgemm<1><<<dim3(1, (NN + 127) / 128), 256>>>(x, W1, as1, ad1);

    // ---- join, then the serial chain ----
    cudaStreamWaitEvent(0, e1, 0);
    k_gather<1><<<(NN + 7) / 8, 256>>>(b1, nullptr, nullptr, nullptr);
    k_sgemm<2><<<dim3(1, (NN + 127) / 128), 256>>>(nullptr, W2, as2, ad2);
    k_gather<2><<<(NN + 7) / 8, 256>>>(b2, Wl, bl, out);
}

// round 6
// speedup vs baseline: 3.2420x; 1.1032x over previous
#include <cuda_runtime.h>
#include <cuda_fp16.h>
#include <math.h>

#define NN   50000
#define EE   1600000
#define MM   (EE + NN)
#define IND  256
#define HIDD 64
#define NH1  2
#define F1   128        // NH1*HIDD
#define NCLS 10
#define NEG  0.2f

#define SCAN_B 196      // ceil(NN/256)

// ---------------- scratch (static device globals; no allocation) ------------
__device__ __half g_h1[NN * F1];        // fp16 message features (layer 1)
__device__ __half g_h2[NN * HIDD];      // fp16 message features (layer 2)
__device__ float g_as1[NN * NH1], g_ad1[NN * NH1];
__device__ float g_x2[NN * F1];         // fp32 input to GEMM2
__device__ float g_as2[NN], g_ad2[NN];

// CSR scratch (built once per call; shared by both layers)
__device__ int g_cnt[NN];
__device__ int g_part[SCAN_B];
__device__ int g_off[SCAN_B];
__device__ int g_ptr[NN + 1];
__device__ int g_cur[NN];
__device__ int g_csrc[MM];

// ---------------- helpers ----------------------------------------------------
__device__ __forceinline__ float lrelu(float x) { return x > 0.f ? x : NEG * x; }
__device__ __forceinline__ float eluf(float x)  { return x > 0.f ? x : (__expf(x) - 1.f); }

union F2U { float2 f; unsigned long long u; };
// packed dual fp32 FMA: d.lo += a.lo*b.lo ; d.hi += a.hi*b.hi  (sm_103a)
__device__ __forceinline__ void ffma2(F2U& d, const F2U& a, const F2U& b) {
    asm("fma.rn.f32x2 %0, %1, %2, %0;" : "+l"(d.u) : "l"(a.u), "l"(b.u));
}

// ---------------- CSR build ---------------------------------------------------
__global__ void k_count(const int* __restrict__ ei) {
    int m4 = blockIdx.x * blockDim.x + threadIdx.x;
    if (m4 < EE / 4) {
        int4 d = ((const int4*)(ei + EE))[m4];
        atomicAdd(&g_cnt[d.x], 1);
        atomicAdd(&g_cnt[d.y], 1);
        atomicAdd(&g_cnt[d.z], 1);
        atomicAdd(&g_cnt[d.w], 1);
    }
}

// phase 1: per-block sums of (cnt[i]+1)  [+1 folds in the self-loop]
__global__ void k_scan1() {
    __shared__ int sw[8];
    int i = blockIdx.x * 256 + threadIdx.x;
    int v = (i < NN) ? (g_cnt[i] + 1) : 0;
    int s = v;
    #pragma unroll
    for (int o = 16; o; o >>= 1) s += __shfl_xor_sync(0xffffffffu, s, o);
    if ((threadIdx.x & 31) == 0) sw[threadIdx.x >> 5] = s;
    __syncthreads();
    if (threadIdx.x == 0) {
        int t = 0;
        #pragma unroll
        for (int w = 0; w < 8; w++) t += sw[w];
        g_part[blockIdx.x] = t;
    }
}

// phase 2: single-block exclusive scan of SCAN_B partials
__global__ void k_scan2() {
    __shared__ int sh[256];
    int t = threadIdx.x;
    int v = (t < SCAN_B) ? g_part[t] : 0;
    sh[t] = v;
    __syncthreads();
    for (int off = 1; off < 256; off <<= 1) {
        int u = (t >= off) ? sh[t - off] : 0;
        __syncthreads();
        sh[t] += u;
        __syncthreads();
    }
    if (t < SCAN_B) g_off[t] = sh[t] - v;       // exclusive
    if (t == 255) g_ptr[NN] = sh[255];          // total = MM
}

// phase 3: in-block exclusive scan + global offset; write ptr & cur
__global__ void k_scan3() {
    __shared__ int sw[8];
    int t = threadIdx.x;
    int i = blockIdx.x * 256 + t;
    int v = (i < NN) ? (g_cnt[i] + 1) : 0;
    int lane = t & 31, w = t >> 5;
    int s = v;
    #pragma unroll
    for (int o = 1; o < 32; o <<= 1) {
        int u = __shfl_up_sync(0xffffffffu, s, o);
        if (lane >= o) s += u;
    }
    if (lane == 31) sw[w] = s;
    __syncthreads();
    if (t < 8) {
        int u = sw[t];
        #pragma unroll
        for (int o = 1; o < 8; o <<= 1) {
            int uu = __shfl_up_sync(0xffu, u, o);
            if (t >= o) u += uu;
        }
        sw[t] = u;
    }
    __syncthreads();
    int excl = s - v + (w ? sw[w - 1] : 0) + g_off[blockIdx.x];
    if (i < NN) { g_ptr[i] = excl; g_cur[i] = excl; }
}

__global__ void k_scatter(const int* __restrict__ ei) {
    int m4 = blockIdx.x * blockDim.x + threadIdx.x;
    if (m4 < EE / 4) {
        int4 s = ((const int4*)ei)[m4];
        int4 d = ((const int4*)(ei + EE))[m4];
        g_csrc[atomicAdd(&g_cur[d.x], 1)] = s.x;
        g_csrc[atomicAdd(&g_cur[d.y], 1)] = s.y;
        g_csrc[atomicAdd(&g_cur[d.z], 1)] = s.z;
        g_csrc[atomicAdd(&g_cur[d.w], 1)] = s.w;
    } else {
        int n = m4 - EE / 4;
        if (n < NN) g_csrc[atomicAdd(&g_cur[n], 1)] = n;  // self-loop
    }
}

// ---------------- f32x2 GEMM + fused attention-dot epilogue ------------------
// C[NN,Nc] = A[NN,K] @ B[K,Nc]; BM=128, BN=Nc, BK=16, 256 threads.
// C is stored as fp16 (message features); attention dots computed in fp32.
template <int L>
__global__ void __launch_bounds__(256) k_sgemm(
        const float* __restrict__ Ain, const float* __restrict__ B,
        const float* __restrict__ att_s, const float* __restrict__ att_d) {
    constexpr int K  = (L == 1) ? IND : F1;
    constexpr int Nc = (L == 1) ? F1  : HIDD;
    constexpr int H  = (L == 1) ? NH1 : 1;
    constexpr int TN = Nc / 16;           // 8 (L1) / 4 (L2)
    constexpr int NT = K / 16;            // k-tiles
    constexpr int BV = (16 * Nc / 4) / 256;  // B float4s per thread: 2 / 1
    const float* A = (L == 1) ? Ain : (const float*)g_x2;
    __half* C  = (L == 1) ? g_h1 : g_h2;
    float* as_ = (L == 1) ? g_as1 : g_as2;
    float* ad_ = (L == 1) ? g_ad1 : g_ad2;

    __shared__ float As[16 * 128];   // transposed: As[k][row]
    __shared__ float Bs[16 * Nc];    // row-major:  Bs[k][col]

    int tid = threadIdx.x;
    int tx = tid & 15, ty = tid >> 4;
    int lane = tid & 31;
    int row0 = blockIdx.y * 128;

    float4 pa[2], pb[2];

    auto loadA = [&](int t) {
        int k0 = t * 16;
        #pragma unroll
        for (int p = 0; p < 2; p++) {
            int idx = tid + p * 256;
            int r = idx >> 2, c4 = idx & 3;
            int gr = row0 + r;
            pa[p] = (gr < NN) ? *(const float4*)&A[(size_t)gr * K + k0 + c4 * 4]
                              : make_float4(0.f, 0.f, 0.f, 0.f);
        }
    };
    auto loadB = [&](int t) {
        int k0 = t * 16;
        #pragma unroll
        for (int p = 0; p < BV; p++) {
            int idx = tid + p * 256;
            int r = idx / (Nc / 4), c4 = idx % (Nc / 4);
            pb[p] = *(const float4*)&B[(size_t)(k0 + r) * Nc + c4 * 4];
        }
    };
    auto stageA = [&]() {
        #pragma unroll
        for (int p = 0; p < 2; p++) {
            int idx = tid + p * 256;
            int r = idx >> 2, c4 = idx & 3;
            As[(c4 * 4 + 0) * 128 + r] = pa[p].x;
            As[(c4 * 4 + 1) * 128 + r] = pa[p].y;
            As[(c4 * 4 + 2) * 128 + r] = pa[p].z;
            As[(c4 * 4 + 3) * 128 + r] = pa[p].w;
        }
    };
    auto stageB = [&]() {
        #pragma unroll
        for (int p = 0; p < BV; p++) {
            int idx = tid + p * 256;
            int r = idx / (Nc / 4), c4 = idx % (Nc / 4);
            *(float4*)&Bs[r * Nc + c4 * 4] = pb[p];
        }
    };

    F2U acc[4][TN];
    #pragma unroll
    for (int i = 0; i < 4; i++)
        #pragma unroll
        for (int j = 0; j < TN; j++) acc[i][j].f = make_float2(0.f, 0.f);

    loadA(0); loadB(0);
    stageA(); stageB();
    __syncthreads();

    for (int t = 0; t < NT; t++) {
        if (t + 1 < NT) { loadA(t + 1); loadB(t + 1); }
        #pragma unroll
        for (int kk = 0; kk < 16; kk++) {
            ulonglong2 av0 = *(const ulonglong2*)&As[kk * 128 + ty * 8];
            ulonglong2 av1 = *(const ulonglong2*)&As[kk * 128 + ty * 8 + 4];
            F2U ap[4];
            ap[0].u = av0.x; ap[1].u = av0.y; ap[2].u = av1.x; ap[3].u = av1.y;
            float bv[TN];
            #pragma unroll
            for (int q = 0; q < TN / 4; q++)
                *(float4*)&bv[q * 4] = *(const float4*)&Bs[kk * Nc + tx * TN + q * 4];
            #pragma unroll
            for (int j = 0; j < TN; j++) {
                F2U bb; bb.f = make_float2(bv[j], bv[j]);
                #pragma unroll
                for (int i2 = 0; i2 < 4; i2++) ffma2(acc[i2][j], ap[i2], bb);
            }
        }
        __syncthreads();
        if (t + 1 < NT) { stageA(); stageB(); __syncthreads(); }
    }

    // store C as fp16 (two rows per acc pair)
    #pragma unroll
    for (int i2 = 0; i2 < 4; i2++) {
        #pragma unroll
        for (int p = 0; p < 2; p++) {
            int gr = row0 + ty * 8 + 2 * i2 + p;
            if (gr < NN) {
                __half2 hv[4];
                #pragma unroll
                for (int q = 0; q < TN / 2; q++) {
                    float a = p ? acc[i2][2 * q].f.y     : acc[i2][2 * q].f.x;
                    float b = p ? acc[i2][2 * q + 1].f.y : acc[i2][2 * q + 1].f.x;
                    hv[q] = __floats2half2_rn(a, b);
                }
                __half* dst = &C[(size_t)gr * Nc + tx * TN];
                if (TN == 8) *(uint4*)dst = *(uint4*)hv;
                else         *(uint2*)dst = *(uint2*)hv;
            }
        }
    }

    // fused attention dots (fp32, from fp32 accumulators)
    constexpr int W = (L == 1) ? 8 : 16;   // lanes per head group
    float vs[TN], vd[TN];
    #pragma unroll
    for (int j = 0; j < TN; j++) {
        vs[j] = att_s[tx * TN + j];
        vd[j] = att_d[tx * TN + j];
    }
    #pragma unroll
    for (int i2 = 0; i2 < 4; i2++) {
        #pragma unroll
        for (int p = 0; p < 2; p++) {
            float ps = 0.f, pd = 0.f;
            #pragma unroll
            for (int j = 0; j < TN; j++) {
                float av = p ? acc[i2][j].f.y : acc[i2][j].f.x;
                ps += av * vs[j];
                pd += av * vd[j];
            }
            #pragma unroll
            for (int o = W / 2; o; o >>= 1) {
                ps += __shfl_down_sync(0xffffffffu, ps, o, W);
                pd += __shfl_down_sync(0xffffffffu, pd, o, W);
            }
            if ((lane % W) == 0) {
                int gr = row0 + ty * 8 + 2 * i2 + p;
                int head = (L == 1) ? (tx >> 3) : 0;
                if (gr < NN) { as_[gr * H + head] = ps; ad_[gr * H + head] = pd; }
            }
        }
    }
}

// ---------------- fused softmax + aggregation + bias + ELU (warp per node) ---
// L==2 additionally fuses the classifier head: out = elu(agg+b2) @ Wl + bl.
template <int L>
__global__ void k_gather(const float* __restrict__ bias,
                         const float* __restrict__ Wl, const float* __restrict__ bl,
                         float* __restrict__ out) {
    constexpr int H = (L == 1) ? NH1 : 1;
    constexpr int F = H * HIDD;
    constexpr int VEC = F / 32;              // 4 (L1) or 2 (L2)
    const float* as_ = (L == 1) ? g_as1 : g_as2;
    const float* ad_ = (L == 1) ? g_ad1 : g_ad2;
    const __half* h  = (L == 1) ? (const __half*)g_h1 : (const __half*)g_h2;

    int n = (blockIdx.x * blockDim.x + threadIdx.x) >> 5;
    int lane = threadIdx.x & 31;
    if (n >= NN) return;

    int beg = g_ptr[n], end = g_ptr[n + 1];
    float ad0 = ad_[n * H];
    float ad1 = (H == 2) ? ad_[n * H + 1] : 0.f;

    float acc[VEC];
    #pragma unroll
    for (int v = 0; v < VEC; v++) acc[v] = 0.f;
    float d0 = 0.f, d1 = 0.f;

    for (int c = beg; c < end; c += 32) {
        int m = c + lane;
        int src = 0;
        float ex0 = 0.f, ex1 = 0.f;
        if (m < end) {
            src = g_csrc[m];
            ex0 = __expf(lrelu(as_[src * H] + ad0));
            if (H == 2) ex1 = __expf(lrelu(as_[src * H + 1] + ad1));
        }
        d0 += ex0; d1 += ex1;
        int cnt = min(32, end - c);
        #pragma unroll 4
        for (int j = 0; j < cnt; j++) {
            int s = __shfl_sync(0xffffffffu, src, j);
            float w0 = __shfl_sync(0xffffffffu, ex0, j);
            float w;
            if (H == 2) {
                float w1 = __shfl_sync(0xffffffffu, ex1, j);
                w = (lane < 16) ? w0 : w1;
            } else {
                w = w0;
            }
            if (VEC == 4) {
                uint2 raw = *(const uint2*)(h + (size_t)s * F + lane * 4);
                float2 f0 = __half22float2(*(__half2*)&raw.x);
                float2 f1 = __half22float2(*(__half2*)&raw.y);
                acc[0] += w * f0.x; acc[1] += w * f0.y;
                acc[2] += w * f1.x; acc[3] += w * f1.y;
            } else {
                float2 f0 = __half22float2(*(const __half2*)(h + (size_t)s * F + lane * 2));
                acc[0] += w * f0.x; acc[1] += w * f0.y;
            }
        }
    }
    #pragma unroll
    for (int o = 16; o; o >>= 1) {
        d0 += __shfl_xor_sync(0xffffffffu, d0, o);
        if (H == 2) d1 += __shfl_xor_sync(0xffffffffu, d1, o);
    }
    float denom = (H == 2) ? ((lane < 16) ? d0 : d1) : d0;
    float inv = 1.f / denom;

    if (L == 1) {
        float4 o_;
        o_.x = eluf(acc[0] * inv + bias[lane * 4 + 0]);
        o_.y = eluf(acc[1] * inv + bias[lane * 4 + 1]);
        o_.z = eluf(acc[2] * inv + bias[lane * 4 + 2]);
        o_.w = eluf(acc[3] * inv + bias[lane * 4 + 3]);
        *(float4*)(g_x2 + (size_t)n * F + lane * 4) = o_;
    } else {
        float v0 = eluf(acc[0] * inv + bias[lane * 2 + 0]);
        float v1 = eluf(acc[1] * inv + bias[lane * 2 + 1]);
        int f0 = lane * 2, f1 = lane * 2 + 1;
        float cls[NCLS];
        #pragma unroll
        for (int j = 0; j < NCLS; j++)
            cls[j] = v0 * Wl[f0 * NCLS + j] + v1 * Wl[f1 * NCLS + j];
        #pragma unroll
        for (int o = 16; o; o >>= 1)
            #pragma unroll
            for (int j = 0; j < NCLS; j++)
                cls[j] += __shfl_xor_sync(0xffffffffu, cls[j], o);
        if (lane == 0) {
            #pragma unroll
            for (int j = 0; j < NCLS; j++)
                out[(size_t)n * NCLS + j] = cls[j] + bl[j];
        }
    }
}

// ---------------- launch ------------------------------------------------------
extern "C" void kernel_launch(void* const* d_in, const int* in_sizes, int n_in,
                              void* d_out, int out_size) {
    const float* x   = (const float*)d_in[0];
    const int*   ei  = (const int*)d_in[1];
    const float* W1  = (const float*)d_in[2];
    const float* as1 = (const float*)d_in[3];
    const float* ad1 = (const float*)d_in[4];
    const float* b1  = (const float*)d_in[5];
    const float* W2  = (const float*)d_in[6];
    const float* as2 = (const float*)d_in[7];
    const float* ad2 = (const float*)d_in[8];
    const float* b2  = (const float*)d_in[9];
    const float* Wl  = (const float*)d_in[10];
    const float* bl  = (const float*)d_in[11];
    float* out = (float*)d_out;

    // one-time infra (created on the eager correctness call, reused thereafter;
    // no device memory is allocated)
    static cudaStream_t s2 = nullptr;
    static cudaEvent_t e0 = nullptr, e1 = nullptr;
    static void* cnt_addr = nullptr;
    if (!s2) {
        cudaStreamCreateWithFlags(&s2, cudaStreamNonBlocking);
        cudaEventCreateWithFlags(&e0, cudaEventDisableTiming);
        cudaEventCreateWithFlags(&e1, cudaEventDisableTiming);
        cudaGetSymbolAddress(&cnt_addr, g_cnt);
    }

    const int T = 256;
    // ---- fork: CSR build on side stream, GEMM1 on main stream ----
    cudaEventRecord(e0, 0);
    cudaStreamWaitEvent(s2, e0, 0);
    cudaMemsetAsync(cnt_addr, 0, NN * sizeof(int), s2);
    k_count<<<(EE / 4 + T - 1) / T, T, 0, s2>>>(ei);
    k_scan1<<<SCAN_B, 256, 0, s2>>>();
    k_scan2<<<1, 256, 0, s2>>>();
    k_scan3<<<SCAN_B, 256, 0, s2>>>();
    k_scatter<<<(EE / 4 + NN + T - 1) / T, T, 0, s2>>>(ei);
    cudaEventRecord(e1, s2);

    k_sgemm<1><<<dim3(1, (NN + 127) / 128), 256>>>(x, W1, as1, ad1);

    // ---- join, then the serial chain ----
    cudaStreamWaitEvent(0, e1, 0);
    k_gather<1><<<(NN + 7) / 8, 256>>>(b1, nullptr, nullptr, nullptr);
    k_sgemm<2><<<dim3(1, (NN + 127) / 128), 256>>>(nullptr, W2, as2, ad2);
    k_gather<2><<<(NN + 7) / 8, 256>>>(b2, Wl, bl, out);
}

// round 8
// speedup vs baseline: 4.2009x; 1.2958x over previous
#include <cuda_runtime.h>
#include <cuda_fp16.h>
#include <stdint.h>
#include <math.h>

#define NN   50000
#define EE   1600000
#define MM   (EE + NN)
#define IND  256
#define HIDD 64
#define NH1  2
#define F1   128        // NH1*HIDD
#define NCLS 10
#define NEG  0.2f

#define SCAN_B 196      // ceil(NN/256)

// ---------------- scratch (static device globals; no allocation) ------------
__device__ __half g_h1[NN * F1];        // fp16 message features (layer 1)
__device__ __half g_h2[NN * HIDD];      // fp16 message features (layer 2)
__device__ float g_as1[NN * NH1], g_ad1[NN * NH1];
__device__ float g_x2[NN * F1];         // fp32 input to GEMM2
__device__ float g_as2[NN], g_ad2[NN];

// CSR scratch (built once per call; shared by both layers)
__device__ int g_cnt[NN];
__device__ int g_part[SCAN_B];
__device__ int g_off[SCAN_B];
__device__ int g_ptr[NN + 1];
__device__ int g_cur[NN];
__device__ int g_csrc[MM];

// ---------------- helpers ----------------------------------------------------
__device__ __forceinline__ float lrelu(float x) { return x > 0.f ? x : NEG * x; }
__device__ __forceinline__ float eluf(float x)  { return x > 0.f ? x : (__expf(x) - 1.f); }

__device__ __forceinline__ uint32_t smem_u32(const void* p) {
    return (uint32_t)__cvta_generic_to_shared(p);
}
__device__ __forceinline__ void ldsm_x4(uint32_t* r, uint32_t addr) {
    asm volatile("ldmatrix.sync.aligned.m8n8.x4.shared.b16 {%0,%1,%2,%3}, [%4];"
                 : "=r"(r[0]), "=r"(r[1]), "=r"(r[2]), "=r"(r[3]) : "r"(addr));
}
__device__ __forceinline__ void ldsm_x4t(uint32_t* r, uint32_t addr) {
    asm volatile("ldmatrix.sync.aligned.m8n8.x4.trans.shared.b16 {%0,%1,%2,%3}, [%4];"
                 : "=r"(r[0]), "=r"(r[1]), "=r"(r[2]), "=r"(r[3]) : "r"(addr));
}
__device__ __forceinline__ void mma16816(float* d, const uint32_t* a, uint32_t b0, uint32_t b1) {
    asm volatile(
        "mma.sync.aligned.m16n8k16.row.col.f32.f16.f16.f32 "
        "{%0,%1,%2,%3}, {%4,%5,%6,%7}, {%8,%9}, {%0,%1,%2,%3};"
        : "+f"(d[0]), "+f"(d[1]), "+f"(d[2]), "+f"(d[3])
        : "r"(a[0]), "r"(a[1]), "r"(a[2]), "r"(a[3]), "r"(b0), "r"(b1));
}
__device__ __forceinline__ uint2 cvt_half4(float4 v) {
    __half2 lo = __floats2half2_rn(v.x, v.y);
    __half2 hi = __floats2half2_rn(v.z, v.w);
    uint2 r;
    r.x = *(uint32_t*)&lo;
    r.y = *(uint32_t*)&hi;
    return r;
}

// ---------------- CSR build ---------------------------------------------------
__global__ void k_count(const int* __restrict__ ei) {
    int m4 = blockIdx.x * blockDim.x + threadIdx.x;
    if (m4 < EE / 4) {
        int4 d = ((const int4*)(ei + EE))[m4];
        atomicAdd(&g_cnt[d.x], 1);
        atomicAdd(&g_cnt[d.y], 1);
        atomicAdd(&g_cnt[d.z], 1);
        atomicAdd(&g_cnt[d.w], 1);
    }
}

__global__ void k_scan1() {
    __shared__ int sw[8];
    int i = blockIdx.x * 256 + threadIdx.x;
    int v = (i < NN) ? (g_cnt[i] + 1) : 0;
    int s = v;
    #pragma unroll
    for (int o = 16; o; o >>= 1) s += __shfl_xor_sync(0xffffffffu, s, o);
    if ((threadIdx.x & 31) == 0) sw[threadIdx.x >> 5] = s;
    __syncthreads();
    if (threadIdx.x == 0) {
        int t = 0;
        #pragma unroll
        for (int w = 0; w < 8; w++) t += sw[w];
        g_part[blockIdx.x] = t;
    }
}

__global__ void k_scan2() {
    __shared__ int sh[256];
    int t = threadIdx.x;
    int v = (t < SCAN_B) ? g_part[t] : 0;
    sh[t] = v;
    __syncthreads();
    for (int off = 1; off < 256; off <<= 1) {
        int u = (t >= off) ? sh[t - off] : 0;
        __syncthreads();
        sh[t] += u;
        __syncthreads();
    }
    if (t < SCAN_B) g_off[t] = sh[t] - v;
    if (t == 255) g_ptr[NN] = sh[255];
}

__global__ void k_scan3() {
    __shared__ int sw[8];
    int t = threadIdx.x;
    int i = blockIdx.x * 256 + t;
    int v = (i < NN) ? (g_cnt[i] + 1) : 0;
    int lane = t & 31, w = t >> 5;
    int s = v;
    #pragma unroll
    for (int o = 1; o < 32; o <<= 1) {
        int u = __shfl_up_sync(0xffffffffu, s, o);
        if (lane >= o) s += u;
    }
    if (lane == 31) sw[w] = s;
    __syncthreads();
    if (t < 8) {
        int u = sw[t];
        #pragma unroll
        for (int o = 1; o < 8; o <<= 1) {
            int uu = __shfl_up_sync(0xffu, u, o);
            if (t >= o) u += uu;
        }
        sw[t] = u;
    }
    __syncthreads();
    int excl = s - v + (w ? sw[w - 1] : 0) + g_off[blockIdx.x];
    if (i < NN) { g_ptr[i] = excl; g_cur[i] = excl; }
}

__global__ void k_scatter(const int* __restrict__ ei) {
    int m4 = blockIdx.x * blockDim.x + threadIdx.x;
    if (m4 < EE / 4) {
        int4 s = ((const int4*)ei)[m4];
        int4 d = ((const int4*)(ei + EE))[m4];
        g_csrc[atomicAdd(&g_cur[d.x], 1)] = s.x;
        g_csrc[atomicAdd(&g_cur[d.y], 1)] = s.y;
        g_csrc[atomicAdd(&g_cur[d.z], 1)] = s.z;
        g_csrc[atomicAdd(&g_cur[d.w], 1)] = s.w;
    } else {
        int n = m4 - EE / 4;
        if (n < NN) g_csrc[atomicAdd(&g_cur[n], 1)] = n;  // self-loop
    }
}

// ---------------- HMMA fp16 GEMM + fused attention-dot epilogue --------------
// C[NN,Nc] = A[NN,K] @ B[K,Nc]. BM=128, BN=Nc, BK=32, 256 threads (8 warps,
// warp w owns rows w*16..w*16+15). A/B converted fp32->fp16 while staging;
// accumulate fp32 via mma.m16n8k16; C stored fp16; attention dots from fp32 acc.
template <int L>
__global__ void __launch_bounds__(256) k_hgemm(
        const float* __restrict__ Ain, const float* __restrict__ B,
        const float* __restrict__ att_s, const float* __restrict__ att_d) {
    constexpr int K   = (L == 1) ? IND : F1;
    constexpr int Nc  = (L == 1) ? F1  : HIDD;
    constexpr int H   = (L == 1) ? NH1 : 1;
    constexpr int NT  = K / 32;          // k-tiles
    constexpr int NI  = Nc / 8;          // n8 tiles per warp row
    constexpr int LDA = 40;              // halves (conflict-free, 16B-mult stride)
    constexpr int LDB = Nc + 8;          // halves
    constexpr int APT = 4;               // A float4 per thread (128*32/4/256)
    constexpr int BPT = (32 * Nc / 4) / 256;  // B float4 per thread: 4 / 2
    const float* A = (L == 1) ? Ain : (const float*)g_x2;
    __half* C  = (L == 1) ? g_h1 : g_h2;
    float* as_ = (L == 1) ? g_as1 : g_as2;
    float* ad_ = (L == 1) ? g_ad1 : g_ad2;

    __shared__ __align__(16) __half As[2][128 * LDA];
    __shared__ __align__(16) __half Bs[2][32 * LDB];

    int tid = threadIdx.x;
    int w = tid >> 5, lane = tid & 31;
    int g = lane >> 2, t4 = lane & 3;
    int row0 = blockIdx.x * 128;

    uint2 pa[APT], pb[BPT];

    auto loadTile = [&](int t) {
        int k0 = t * 32;
        #pragma unroll
        for (int p = 0; p < APT; p++) {
            int idx = tid + p * 256;
            int r = idx >> 3, c4 = idx & 7;          // 8 float4 per 32-wide row
            int gr = row0 + r;
            float4 v = (gr < NN) ? *(const float4*)&A[(size_t)gr * K + k0 + c4 * 4]
                                 : make_float4(0.f, 0.f, 0.f, 0.f);
            pa[p] = cvt_half4(v);
        }
        #pragma unroll
        for (int p = 0; p < BPT; p++) {
            int idx = tid + p * 256;
            int r = idx / (Nc / 4), c4 = idx % (Nc / 4);
            pb[p] = cvt_half4(*(const float4*)&B[(size_t)(k0 + r) * Nc + c4 * 4]);
        }
    };
    auto stageTile = [&](int buf) {
        #pragma unroll
        for (int p = 0; p < APT; p++) {
            int idx = tid + p * 256;
            int r = idx >> 3, c4 = idx & 7;
            *(uint2*)&As[buf][r * LDA + c4 * 4] = pa[p];
        }
        #pragma unroll
        for (int p = 0; p < BPT; p++) {
            int idx = tid + p * 256;
            int r = idx / (Nc / 4), c4 = idx % (Nc / 4);
            *(uint2*)&Bs[buf][r * LDB + c4 * 4] = pb[p];
        }
    };

    float acc[NI][4];
    #pragma unroll
    for (int i = 0; i < NI; i++)
        #pragma unroll
        for (int j = 0; j < 4; j++) acc[i][j] = 0.f;

    loadTile(0);
    stageTile(0);
    __syncthreads();

    for (int t = 0; t < NT; t++) {
        if (t + 1 < NT) loadTile(t + 1);
        int buf = t & 1;
        #pragma unroll
        for (int ks = 0; ks < 2; ks++) {
            uint32_t a[4];
            ldsm_x4(a, smem_u32(&As[buf][(w * 16 + (lane & 15)) * LDA
                                         + ks * 16 + (lane >> 4) * 8]));
            #pragma unroll
            for (int nt = 0; nt < Nc / 16; nt++) {
                uint32_t b[4];
                ldsm_x4t(b, smem_u32(&Bs[buf][(ks * 16 + (lane & 15)) * LDB
                                              + nt * 16 + (lane >> 4) * 8]));
                mma16816(acc[2 * nt],     a, b[0], b[1]);
                mma16816(acc[2 * nt + 1], a, b[2], b[3]);
            }
        }
        if (t + 1 < NT) {
            stageTile((t + 1) & 1);
            __syncthreads();
        }
    }

    // ---- store C as fp16 (rows r0 and r0+8 per quad) ----
    int r0 = row0 + w * 16 + g;
    #pragma unroll
    for (int ni = 0; ni < NI; ni++) {
        if (r0 < NN) {
            __half2 v = __floats2half2_rn(acc[ni][0], acc[ni][1]);
            *(__half2*)&C[(size_t)r0 * Nc + ni * 8 + t4 * 2] = v;
        }
        if (r0 + 8 < NN) {
            __half2 v = __floats2half2_rn(acc[ni][2], acc[ni][3]);
            *(__half2*)&C[(size_t)(r0 + 8) * Nc + ni * 8 + t4 * 2] = v;
        }
    }

    // ---- fused attention dots (per head, reduce over the 4-lane quad) ----
    #pragma unroll
    for (int hh = 0; hh < H; hh++) {
        float s0 = 0.f, d0 = 0.f, s1 = 0.f, d1 = 0.f;
        #pragma unroll
        for (int ntl = 0; ntl < 8; ntl++) {
            int ni = hh * 8 + ntl;
            int lc = ntl * 8 + t4 * 2;
            float w0s = att_s[hh * 64 + lc],  w1s = att_s[hh * 64 + lc + 1];
            float w0d = att_d[hh * 64 + lc],  w1d = att_d[hh * 64 + lc + 1];
            s0 += acc[ni][0] * w0s + acc[ni][1] * w1s;
            d0 += acc[ni][0] * w0d + acc[ni][1] * w1d;
            s1 += acc[ni][2] * w0s + acc[ni][3] * w1s;
            d1 += acc[ni][2] * w0d + acc[ni][3] * w1d;
        }
        #pragma unroll
        for (int o = 1; o <= 2; o <<= 1) {
            s0 += __shfl_xor_sync(0xffffffffu, s0, o);
            d0 += __shfl_xor_sync(0xffffffffu, d0, o);
            s1 += __shfl_xor_sync(0xffffffffu, s1, o);
            d1 += __shfl_xor_sync(0xffffffffu, d1, o);
        }
        if (t4 == 0) {
            if (r0 < NN)     { as_[r0 * H + hh] = s0;       ad_[r0 * H + hh] = d0; }
            if (r0 + 8 < NN) { as_[(r0 + 8) * H + hh] = s1; ad_[(r0 + 8) * H + hh] = d1; }
        }
    }
}

// ---------------- fused softmax + aggregation + bias + ELU (warp per node) ---
// L==2 additionally fuses the classifier head: out = elu(agg+b2) @ Wl + bl.
template <int L>
__global__ void k_gather(const float* __restrict__ bias,
                         const float* __restrict__ Wl, const float* __restrict__ bl,
                         float* __restrict__ out) {
    constexpr int H = (L == 1) ? NH1 : 1;
    constexpr int F = H * HIDD;
    constexpr int VEC = F / 32;              // 4 (L1) or 2 (L2)
    const float* as_ = (L == 1) ? g_as1 : g_as2;
    const float* ad_ = (L == 1) ? g_ad1 : g_ad2;
    const __half* h  = (L == 1) ? (const __half*)g_h1 : (const __half*)g_h2;

    int n = (blockIdx.x * blockDim.x + threadIdx.x) >> 5;
    int lane = threadIdx.x & 31;
    if (n >= NN) return;

    int beg = g_ptr[n], end = g_ptr[n + 1];
    float ad0 = ad_[n * H];
    float ad1 = (H == 2) ? ad_[n * H + 1] : 0.f;

    float acc[VEC];
    #pragma unroll
    for (int v = 0; v < VEC; v++) acc[v] = 0.f;
    float d0 = 0.f, d1 = 0.f;

    for (int c = beg; c < end; c += 32) {
        int m = c + lane;
        int src = 0;
        float ex0 = 0.f, ex1 = 0.f;
        if (m < end) {
            src = g_csrc[m];
            ex0 = __expf(lrelu(as_[src * H] + ad0));
            if (H == 2) ex1 = __expf(lrelu(as_[src * H + 1] + ad1));
        }
        d0 += ex0; d1 += ex1;
        int cnt = min(32, end - c);
        #pragma unroll 4
        for (int j = 0; j < cnt; j++) {
            int s = __shfl_sync(0xffffffffu, src, j);
            float w0 = __shfl_sync(0xffffffffu, ex0, j);
            float w;
            if (H == 2) {
                float w1 = __shfl_sync(0xffffffffu, ex1, j);
                w = (lane < 16) ? w0 : w1;
            } else {
                w = w0;
            }
            if (VEC == 4) {
                uint2 raw = *(const uint2*)(h + (size_t)s * F + lane * 4);
                float2 f0 = __half22float2(*(__half2*)&raw.x);
                float2 f1 = __half22float2(*(__half2*)&raw.y);
                acc[0] += w * f0.x; acc[1] += w * f0.y;
                acc[2] += w * f1.x; acc[3] += w * f1.y;
            } else {
                float2 f0 = __half22float2(*(const __half2*)(h + (size_t)s * F + lane * 2));
                acc[0] += w * f0.x; acc[1] += w * f0.y;
            }
        }
    }
    #pragma unroll
    for (int o = 16; o; o >>= 1) {
        d0 += __shfl_xor_sync(0xffffffffu, d0, o);
        if (H == 2) d1 += __shfl_xor_sync(0xffffffffu, d1, o);
    }
    float denom = (H == 2) ? ((lane < 16) ? d0 : d1) : d0;
    float inv = 1.f / denom;

    if (L == 1) {
        float4 o_;
        o_.x = eluf(acc[0] * inv + bias[lane * 4 + 0]);
        o_.y = eluf(acc[1] * inv + bias[lane * 4 + 1]);
        o_.z = eluf(acc[2] * inv + bias[lane * 4 + 2]);
        o_.w = eluf(acc[3] * inv + bias[lane * 4 + 3]);
        *(float4*)(g_x2 + (size_t)n * F + lane * 4) = o_;
    } else {
        float v0 = eluf(acc[0] * inv + bias[lane * 2 + 0]);
        float v1 = eluf(acc[1] * inv + bias[lane * 2 + 1]);
        int f0 = lane * 2, f1 = lane * 2 + 1;
        float cls[NCLS];
        #pragma unroll
        for (int j = 0; j < NCLS; j++)
            cls[j] = v0 * Wl[f0 * NCLS + j] + v1 * Wl[f1 * NCLS + j];
        #pragma unroll
        for (int o = 16; o; o >>= 1)
            #pragma unroll
            for (int j = 0; j < NCLS; j++)
                cls[j] += __shfl_xor_sync(0xffffffffu, cls[j], o);
        if (lane == 0) {
            #pragma unroll
            for (int j = 0; j < NCLS; j++)
                out[(size_t)n * NCLS + j] = cls[j] + bl[j];
        }
    }
}

// ---------------- launch ------------------------------------------------------
extern "C" void kernel_launch(void* const* d_in, const int* in_sizes, int n_in,
                              void* d_out, int out_size) {
    const float* x   = (const float*)d_in[0];
    const int*   ei  = (const int*)d_in[1];
    const float* W1  = (const float*)d_in[2];
    const float* as1 = (const float*)d_in[3];
    const float* ad1 = (const float*)d_in[4];
    const float* b1  = (const float*)d_in[5];
    const float* W2  = (const float*)d_in[6];
    const float* as2 = (const float*)d_in[7];
    const float* ad2 = (const float*)d_in[8];
    const float* b2  = (const float*)d_in[9];
    const float* Wl  = (const float*)d_in[10];
    const float* bl  = (const float*)d_in[11];
    float* out = (float*)d_out;

    // one-time infra (created on the eager correctness call, reused thereafter;
    // no device memory is allocated)
    static cudaStream_t s2 = nullptr;
    static cudaEvent_t e0 = nullptr, e1 = nullptr;
    static void* cnt_addr = nullptr;
    if (!s2) {
        cudaStreamCreateWithFlags(&s2, cudaStreamNonBlocking);
        cudaEventCreateWithFlags(&e0, cudaEventDisableTiming);
        cudaEventCreateWithFlags(&e1, cudaEventDisableTiming);
        cudaGetSymbolAddress(&cnt_addr, g_cnt);
    }

    const int T = 256;
    // ---- fork: CSR build on side stream, GEMM1 on main stream ----
    cudaEventRecord(e0, 0);
    cudaStreamWaitEvent(s2, e0, 0);
    cudaMemsetAsync(cnt_addr, 0, NN * sizeof(int), s2);
    k_count<<<(EE / 4 + T - 1) / T, T, 0, s2>>>(ei);
    k_scan1<<<SCAN_B, 256, 0, s2>>>();
    k_scan2<<<1, 256, 0, s2>>>();
    k_scan3<<<SCAN_B, 256, 0, s2>>>();
    k_scatter<<<(EE / 4 + NN + T - 1) / T, T, 0, s2>>>(ei);
    cudaEventRecord(e1, s2);

    k_hgemm<1><<<(NN + 127) / 128, 256>>>(x, W1, as1, ad1);

    // ---- join, then the serial chain ----
    cudaStreamWaitEvent(0, e1, 0);
    k_gather<1><<<(NN + 7) / 8, 256>>>(b1, nullptr, nullptr, nullptr);
    k_hgemm<2><<<(NN + 127) / 128, 256>>>(nullptr, W2, as2, ad2);
    k_gather<2><<<(NN + 7) / 8, 256>>>(b2, Wl, bl, out);
}

// round 9
// speedup vs baseline: 4.3652x; 1.0391x over previous
#include <cuda_runtime.h>
#include <cuda_fp16.h>
#include <stdint.h>
#include <math.h>

#define NN   50000
#define EE   1600000
#define MM   (EE + NN)
#define IND  256
#define HIDD 64
#define NH1  2
#define F1   128        // NH1*HIDD
#define NCLS 10
#define NEG  0.2f

#define SCAN_B 196      // ceil(NN/256)

// ---------------- scratch (static device globals; no allocation) ------------
__device__ __half g_h1[NN * F1];        // fp16 message features (layer 1)
__device__ __half g_h2[NN * HIDD];      // fp16 message features (layer 2)
__device__ float g_as1[NN * NH1], g_ad1[NN * NH1];
__device__ float g_x2[NN * F1];         // fp32 input to GEMM2
__device__ float g_as2[NN], g_ad2[NN];

// CSR scratch (built once per call; shared by both layers)
__device__ int g_cnt[NN];
__device__ int g_part[SCAN_B];
__device__ int g_off[SCAN_B];
__device__ int g_ptr[NN + 1];
__device__ int g_cur[NN];
__device__ int g_csrc[MM];

// ---------------- helpers ----------------------------------------------------
__device__ __forceinline__ float lrelu(float x) { return x > 0.f ? x : NEG * x; }
__device__ __forceinline__ float eluf(float x)  { return x > 0.f ? x : (__expf(x) - 1.f); }

__device__ __forceinline__ uint32_t smem_u32(const void* p) {
    return (uint32_t)__cvta_generic_to_shared(p);
}
__device__ __forceinline__ void ldsm_x4(uint32_t* r, uint32_t addr) {
    asm volatile("ldmatrix.sync.aligned.m8n8.x4.shared.b16 {%0,%1,%2,%3}, [%4];"
                 : "=r"(r[0]), "=r"(r[1]), "=r"(r[2]), "=r"(r[3]) : "r"(addr));
}
__device__ __forceinline__ void ldsm_x4t(uint32_t* r, uint32_t addr) {
    asm volatile("ldmatrix.sync.aligned.m8n8.x4.trans.shared.b16 {%0,%1,%2,%3}, [%4];"
                 : "=r"(r[0]), "=r"(r[1]), "=r"(r[2]), "=r"(r[3]) : "r"(addr));
}
__device__ __forceinline__ void mma16816(float* d, const uint32_t* a, uint32_t b0, uint32_t b1) {
    asm volatile(
        "mma.sync.aligned.m16n8k16.row.col.f32.f16.f16.f32 "
        "{%0,%1,%2,%3}, {%4,%5,%6,%7}, {%8,%9}, {%0,%1,%2,%3};"
        : "+f"(d[0]), "+f"(d[1]), "+f"(d[2]), "+f"(d[3])
        : "r"(a[0]), "r"(a[1]), "r"(a[2]), "r"(a[3]), "r"(b0), "r"(b1));
}
__device__ __forceinline__ uint2 cvt_half4(float4 v) {
    __half2 lo = __floats2half2_rn(v.x, v.y);
    __half2 hi = __floats2half2_rn(v.z, v.w);
    uint2 r;
    r.x = *(uint32_t*)&lo;
    r.y = *(uint32_t*)&hi;
    return r;
}

// ---------------- CSR build ---------------------------------------------------
__global__ void k_count(const int* __restrict__ ei) {
    int m4 = blockIdx.x * blockDim.x + threadIdx.x;
    if (m4 < EE / 4) {
        int4 d = ((const int4*)(ei + EE))[m4];
        atomicAdd(&g_cnt[d.x], 1);
        atomicAdd(&g_cnt[d.y], 1);
        atomicAdd(&g_cnt[d.z], 1);
        atomicAdd(&g_cnt[d.w], 1);
    }
}

__global__ void k_scan1() {
    __shared__ int sw[8];
    int i = blockIdx.x * 256 + threadIdx.x;
    int v = (i < NN) ? (g_cnt[i] + 1) : 0;
    int s = v;
    #pragma unroll
    for (int o = 16; o; o >>= 1) s += __shfl_xor_sync(0xffffffffu, s, o);
    if ((threadIdx.x & 31) == 0) sw[threadIdx.x >> 5] = s;
    __syncthreads();
    if (threadIdx.x == 0) {
        int t = 0;
        #pragma unroll
        for (int w = 0; w < 8; w++) t += sw[w];
        g_part[blockIdx.x] = t;
    }
}

__global__ void k_scan2() {
    __shared__ int sh[256];
    int t = threadIdx.x;
    int v = (t < SCAN_B) ? g_part[t] : 0;
    sh[t] = v;
    __syncthreads();
    for (int off = 1; off < 256; off <<= 1) {
        int u = (t >= off) ? sh[t - off] : 0;
        __syncthreads();
        sh[t] += u;
        __syncthreads();
    }
    if (t < SCAN_B) g_off[t] = sh[t] - v;
    if (t == 255) g_ptr[NN] = sh[255];
}

__global__ void k_scan3() {
    __shared__ int sw[8];
    int t = threadIdx.x;
    int i = blockIdx.x * 256 + t;
    int v = (i < NN) ? (g_cnt[i] + 1) : 0;
    int lane = t & 31, w = t >> 5;
    int s = v;
    #pragma unroll
    for (int o = 1; o < 32; o <<= 1) {
        int u = __shfl_up_sync(0xffffffffu, s, o);
        if (lane >= o) s += u;
    }
    if (lane == 31) sw[w] = s;
    __syncthreads();
    if (t < 8) {
        int u = sw[t];
        #pragma unroll
        for (int o = 1; o < 8; o <<= 1) {
            int uu = __shfl_up_sync(0xffu, u, o);
            if (t >= o) u += uu;
        }
        sw[t] = u;
    }
    __syncthreads();
    int excl = s - v + (w ? sw[w - 1] : 0) + g_off[blockIdx.x];
    if (i < NN) { g_ptr[i] = excl; g_cur[i] = excl; }
}

__global__ void k_scatter(const int* __restrict__ ei) {
    int m4 = blockIdx.x * blockDim.x + threadIdx.x;
    if (m4 < EE / 4) {
        int4 s = ((const int4*)ei)[m4];
        int4 d = ((const int4*)(ei + EE))[m4];
        g_csrc[atomicAdd(&g_cur[d.x], 1)] = s.x;
        g_csrc[atomicAdd(&g_cur[d.y], 1)] = s.y;
        g_csrc[atomicAdd(&g_cur[d.z], 1)] = s.z;
        g_csrc[atomicAdd(&g_cur[d.w], 1)] = s.w;
    } else {
        int n = m4 - EE / 4;
        if (n < NN) g_csrc[atomicAdd(&g_cur[n], 1)] = n;  // self-loop
    }
}

// ---------------- HMMA fp16 GEMM + fused attention-dot epilogue --------------
template <int L>
__global__ void __launch_bounds__(256) k_hgemm(
        const float* __restrict__ Ain, const float* __restrict__ B,
        const float* __restrict__ att_s, const float* __restrict__ att_d) {
    constexpr int K   = (L == 1) ? IND : F1;
    constexpr int Nc  = (L == 1) ? F1  : HIDD;
    constexpr int H   = (L == 1) ? NH1 : 1;
    constexpr int NT  = K / 32;
    constexpr int NI  = Nc / 8;
    constexpr int LDA = 40;
    constexpr int LDB = Nc + 8;
    constexpr int APT = 4;
    constexpr int BPT = (32 * Nc / 4) / 256;
    const float* A = (L == 1) ? Ain : (const float*)g_x2;
    __half* C  = (L == 1) ? g_h1 : g_h2;
    float* as_ = (L == 1) ? g_as1 : g_as2;
    float* ad_ = (L == 1) ? g_ad1 : g_ad2;

    __shared__ __align__(16) __half As[2][128 * LDA];
    __shared__ __align__(16) __half Bs[2][32 * LDB];

    int tid = threadIdx.x;
    int w = tid >> 5, lane = tid & 31;
    int g = lane >> 2, t4 = lane & 3;
    int row0 = blockIdx.x * 128;

    uint2 pa[APT], pb[BPT];

    auto loadTile = [&](int t) {
        int k0 = t * 32;
        #pragma unroll
        for (int p = 0; p < APT; p++) {
            int idx = tid + p * 256;
            int r = idx >> 3, c4 = idx & 7;
            int gr = row0 + r;
            float4 v = (gr < NN) ? *(const float4*)&A[(size_t)gr * K + k0 + c4 * 4]
                                 : make_float4(0.f, 0.f, 0.f, 0.f);
            pa[p] = cvt_half4(v);
        }
        #pragma unroll
        for (int p = 0; p < BPT; p++) {
            int idx = tid + p * 256;
            int r = idx / (Nc / 4), c4 = idx % (Nc / 4);
            pb[p] = cvt_half4(*(const float4*)&B[(size_t)(k0 + r) * Nc + c4 * 4]);
        }
    };
    auto stageTile = [&](int buf) {
        #pragma unroll
        for (int p = 0; p < APT; p++) {
            int idx = tid + p * 256;
            int r = idx >> 3, c4 = idx & 7;
            *(uint2*)&As[buf][r * LDA + c4 * 4] = pa[p];
        }
        #pragma unroll
        for (int p = 0; p < BPT; p++) {
            int idx = tid + p * 256;
            int r = idx / (Nc / 4), c4 = idx % (Nc / 4);
            *(uint2*)&Bs[buf][r * LDB + c4 * 4] = pb[p];
        }
    };

    float acc[NI][4];
    #pragma unroll
    for (int i = 0; i < NI; i++)
        #pragma unroll
        for (int j = 0; j < 4; j++) acc[i][j] = 0.f;

    loadTile(0);
    stageTile(0);
    __syncthreads();

    for (int t = 0; t < NT; t++) {
        if (t + 1 < NT) loadTile(t + 1);
        int buf = t & 1;
        #pragma unroll
        for (int ks = 0; ks < 2; ks++) {
            uint32_t a[4];
            ldsm_x4(a, smem_u32(&As[buf][(w * 16 + (lane & 15)) * LDA
                                         + ks * 16 + (lane >> 4) * 8]));
            #pragma unroll
            for (int nt = 0; nt < Nc / 16; nt++) {
                uint32_t b[4];
                ldsm_x4t(b, smem_u32(&Bs[buf][(ks * 16 + (lane & 15)) * LDB
                                              + nt * 16 + (lane >> 4) * 8]));
                mma16816(acc[2 * nt],     a, b[0], b[1]);
                mma16816(acc[2 * nt + 1], a, b[2], b[3]);
            }
        }
        if (t + 1 < NT) {
            stageTile((t + 1) & 1);
            __syncthreads();
        }
    }

    int r0 = row0 + w * 16 + g;
    #pragma unroll
    for (int ni = 0; ni < NI; ni++) {
        if (r0 < NN) {
            __half2 v = __floats2half2_rn(acc[ni][0], acc[ni][1]);
            *(__half2*)&C[(size_t)r0 * Nc + ni * 8 + t4 * 2] = v;
        }
        if (r0 + 8 < NN) {
            __half2 v = __floats2half2_rn(acc[ni][2], acc[ni][3]);
            *(__half2*)&C[(size_t)(r0 + 8) * Nc + ni * 8 + t4 * 2] = v;
        }
    }

    #pragma unroll
    for (int hh = 0; hh < H; hh++) {
        float s0 = 0.f, d0 = 0.f, s1 = 0.f, d1 = 0.f;
        #pragma unroll
        for (int ntl = 0; ntl < 8; ntl++) {
            int ni = hh * 8 + ntl;
            int lc = ntl * 8 + t4 * 2;
            float w0s = att_s[hh * 64 + lc],  w1s = att_s[hh * 64 + lc + 1];
            float w0d = att_d[hh * 64 + lc],  w1d = att_d[hh * 64 + lc + 1];
            s0 += acc[ni][0] * w0s + acc[ni][1] * w1s;
            d0 += acc[ni][0] * w0d + acc[ni][1] * w1d;
            s1 += acc[ni][2] * w0s + acc[ni][3] * w1s;
            d1 += acc[ni][2] * w0d + acc[ni][3] * w1d;
        }
        #pragma unroll
        for (int o = 1; o <= 2; o <<= 1) {
            s0 += __shfl_xor_sync(0xffffffffu, s0, o);
            d0 += __shfl_xor_sync(0xffffffffu, d0, o);
            s1 += __shfl_xor_sync(0xffffffffu, s1, o);
            d1 += __shfl_xor_sync(0xffffffffu, d1, o);
        }
        if (t4 == 0) {
            if (r0 < NN)     { as_[r0 * H + hh] = s0;       ad_[r0 * H + hh] = d0; }
            if (r0 + 8 < NN) { as_[(r0 + 8) * H + hh] = s1; ad_[(r0 + 8) * H + hh] = d1; }
        }
    }
}

// ---------------- fused softmax + aggregation + bias + ELU (warp per node) ---
// Full 32-message chunks run a statically-unrolled 8-batched pipeline (MLP=8);
// the <32 remainder uses a generic loop. L==2 fuses the classifier head.
template <int L>
__global__ void k_gather(const float* __restrict__ bias,
                         const float* __restrict__ Wl, const float* __restrict__ bl,
                         float* __restrict__ out) {
    constexpr int H = (L == 1) ? NH1 : 1;
    constexpr int F = H * HIDD;
    constexpr int VEC = F / 32;              // 4 (L1) or 2 (L2)
    const float* as_ = (L == 1) ? g_as1 : g_as2;
    const float* ad_ = (L == 1) ? g_ad1 : g_ad2;
    const __half* h  = (L == 1) ? (const __half*)g_h1 : (const __half*)g_h2;

    int n = (blockIdx.x * blockDim.x + threadIdx.x) >> 5;
    int lane = threadIdx.x & 31;
    if (n >= NN) return;

    int beg = g_ptr[n], end = g_ptr[n + 1];
    float ad0 = ad_[n * H];
    float ad1 = (H == 2) ? ad_[n * H + 1] : 0.f;

    float acc[VEC];
    #pragma unroll
    for (int v = 0; v < VEC; v++) acc[v] = 0.f;
    float d0 = 0.f, d1 = 0.f;

    int c = beg;
    // ---- full 32-message chunks: static unroll, 8 loads in flight ----
    for (; c + 32 <= end; c += 32) {
        int src = g_csrc[c + lane];
        float ex0, ex1 = 0.f;
        if (H == 2) {
            float2 asv = *(const float2*)&as_[src * 2];
            ex0 = __expf(lrelu(asv.x + ad0));
            ex1 = __expf(lrelu(asv.y + ad1));
        } else {
            ex0 = __expf(lrelu(as_[src] + ad0));
        }
        d0 += ex0; d1 += ex1;
        #pragma unroll
        for (int j0 = 0; j0 < 32; j0 += 8) {
            uint2 raw2[8];
            uint32_t raw1[8];
            float wv[8];
            #pragma unroll
            for (int j = 0; j < 8; j++) {
                int s = __shfl_sync(0xffffffffu, src, j0 + j);
                float w0 = __shfl_sync(0xffffffffu, ex0, j0 + j);
                if (H == 2) {
                    float w1 = __shfl_sync(0xffffffffu, ex1, j0 + j);
                    wv[j] = (lane < 16) ? w0 : w1;
                } else {
                    wv[j] = w0;
                }
                if (VEC == 4) raw2[j] = *(const uint2*)(h + (size_t)s * F + lane * 4);
                else          raw1[j] = *(const uint32_t*)(h + (size_t)s * F + lane * 2);
            }
            #pragma unroll
            for (int j = 0; j < 8; j++) {
                if (VEC == 4) {
                    float2 f0 = __half22float2(*(__half2*)&raw2[j].x);
                    float2 f1 = __half22float2(*(__half2*)&raw2[j].y);
                    acc[0] += wv[j] * f0.x; acc[1] += wv[j] * f0.y;
                    acc[2] += wv[j] * f1.x; acc[3] += wv[j] * f1.y;
                } else {
                    float2 f0 = __half22float2(*(__half2*)&raw1[j]);
                    acc[0] += wv[j] * f0.x; acc[1] += wv[j] * f0.y;
                }
            }
        }
    }
    // ---- remainder (<32 messages) ----
    if (c < end) {
        int m = c + lane;
        int src = 0;
        float ex0 = 0.f, ex1 = 0.f;
        if (m < end) {
            src = g_csrc[m];
            ex0 = __expf(lrelu(as_[src * H] + ad0));
            if (H == 2) ex1 = __expf(lrelu(as_[src * H + 1] + ad1));
        }
        d0 += ex0; d1 += ex1;
        int cnt = end - c;
        for (int j = 0; j < cnt; j++) {
            int s = __shfl_sync(0xffffffffu, src, j);
            float w0 = __shfl_sync(0xffffffffu, ex0, j);
            float w;
            if (H == 2) {
                float w1 = __shfl_sync(0xffffffffu, ex1, j);
                w = (lane < 16) ? w0 : w1;
            } else {
                w = w0;
            }
            if (VEC == 4) {
                uint2 raw = *(const uint2*)(h + (size_t)s * F + lane * 4);
                float2 f0 = __half22float2(*(__half2*)&raw.x);
                float2 f1 = __half22float2(*(__half2*)&raw.y);
                acc[0] += w * f0.x; acc[1] += w * f0.y;
                acc[2] += w * f1.x; acc[3] += w * f1.y;
            } else {
                float2 f0 = __half22float2(*(const __half2*)(h + (size_t)s * F + lane * 2));
                acc[0] += w * f0.x; acc[1] += w * f0.y;
            }
        }
    }

    #pragma unroll
    for (int o = 16; o; o >>= 1) {
        d0 += __shfl_xor_sync(0xffffffffu, d0, o);
        if (H == 2) d1 += __shfl_xor_sync(0xffffffffu, d1, o);
    }
    float denom = (H == 2) ? ((lane < 16) ? d0 : d1) : d0;
    float inv = 1.f / denom;

    if (L == 1) {
        float4 o_;
        o_.x = eluf(acc[0] * inv + bias[lane * 4 + 0]);
        o_.y = eluf(acc[1] * inv + bias[lane * 4 + 1]);
        o_.z = eluf(acc[2] * inv + bias[lane * 4 + 2]);
        o_.w = eluf(acc[3] * inv + bias[lane * 4 + 3]);
        *(float4*)(g_x2 + (size_t)n * F + lane * 4) = o_;
    } else {
        float v0 = eluf(acc[0] * inv + bias[lane * 2 + 0]);
        float v1 = eluf(acc[1] * inv + bias[lane * 2 + 1]);
        int f0 = lane * 2, f1 = lane * 2 + 1;
        float cls[NCLS];
        #pragma unroll
        for (int j = 0; j < NCLS; j++)
            cls[j] = v0 * Wl[f0 * NCLS + j] + v1 * Wl[f1 * NCLS + j];
        #pragma unroll
        for (int o = 16; o; o >>= 1)
            #pragma unroll
            for (int j = 0; j < NCLS; j++)
                cls[j] += __shfl_xor_sync(0xffffffffu, cls[j], o);
        if (lane == 0) {
            #pragma unroll
            for (int j = 0; j < NCLS; j++)
                out[(size_t)n * NCLS + j] = cls[j] + bl[j];
        }
    }
}

// ---------------- launch ------------------------------------------------------
extern "C" void kernel_launch(void* const* d_in, const int* in_sizes, int n_in,
                              void* d_out, int out_size) {
    const float* x   = (const float*)d_in[0];
    const int*   ei  = (const int*)d_in[1];
    const float* W1  = (const float*)d_in[2];
    const float* as1 = (const float*)d_in[3];
    const float* ad1 = (const float*)d_in[4];
    const float* b1  = (const float*)d_in[5];
    const float* W2  = (const float*)d_in[6];
    const float* as2 = (const float*)d_in[7];
    const float* ad2 = (const float*)d_in[8];
    const float* b2  = (const float*)d_in[9];
    const float* Wl  = (const float*)d_in[10];
    const float* bl  = (const float*)d_in[11];
    float* out = (float*)d_out;

    static cudaStream_t s2 = nullptr;
    static cudaEvent_t e0 = nullptr, e1 = nullptr;
    static void* cnt_addr = nullptr;
    if (!s2) {
        cudaStreamCreateWithFlags(&s2, cudaStreamNonBlocking);
        cudaEventCreateWithFlags(&e0, cudaEventDisableTiming);
        cudaEventCreateWithFlags(&e1, cudaEventDisableTiming);
        cudaGetSymbolAddress(&cnt_addr, g_cnt);
    }

    const int T = 256;
    // ---- fork: CSR build on side stream, GEMM1 on main stream ----
    cudaEventRecord(e0, 0);
    cudaStreamWaitEvent(s2, e0, 0);
    cudaMemsetAsync(cnt_addr, 0, NN * sizeof(int), s2);
    k_count<<<(EE / 4 + T - 1) / T, T, 0, s2>>>(ei);
    k_scan1<<<SCAN_B, 256, 0, s2>>>();
    k_scan2<<<1, 256, 0, s2>>>();
    k_scan3<<<SCAN_B, 256, 0, s2>>>();
    k_scatter<<<(EE / 4 + NN + T - 1) / T, T, 0, s2>>>(ei);
    cudaEventRecord(e1, s2);

    k_hgemm<1><<<(NN + 127) / 128, 256>>>(x, W1, as1, ad1);

    // ---- join, then the serial chain ----
    cudaStreamWaitEvent(0, e1, 0);
    k_gather<1><<<(NN + 7) / 8, 256>>>(b1, nullptr, nullptr, nullptr);
    k_hgemm<2><<<(NN + 127) / 128, 256>>>(nullptr, W2, as2, ad2);
    k_gather<2><<<(NN + 7) / 8, 256>>>(b2, Wl, bl, out);
}